// round 13
// baseline (speedup 1.0000x reference)
#include <cuda_runtime.h>
#include <cuda_bf16.h>

#define Bb 2
#define Cc 64
#define Hh 256
#define Ww 256
#define HW (Hh*Ww)
#define NUMS 63
#define LL (NUMS*NUMS)          // 3969
#define LLP 4032                // padded L (63*64)
#define K2 64
#define EPSf 1e-5f
#define TBL_W (2*NUMS-1)        // 125
#define NCELL 64

typedef unsigned long long ull;
typedef __nv_bfloat16 bf16;

__device__ __forceinline__ unsigned int smaddr(const void* p){
    return (unsigned int)__cvta_generic_to_shared(p);
}
__device__ __forceinline__ void ldsm4(unsigned int* r, unsigned int addr){
    asm volatile("ldmatrix.sync.aligned.m8n8.x4.shared.b16 {%0,%1,%2,%3}, [%4];"
        : "=r"(r[0]), "=r"(r[1]), "=r"(r[2]), "=r"(r[3]) : "r"(addr));
}
__device__ __forceinline__ void ldsm4t(unsigned int* r, unsigned int addr){
    asm volatile("ldmatrix.sync.aligned.m8n8.x4.trans.shared.b16 {%0,%1,%2,%3}, [%4];"
        : "=r"(r[0]), "=r"(r[1]), "=r"(r[2]), "=r"(r[3]) : "r"(addr));
}
__device__ __forceinline__ void mma16816(float* d, const unsigned int* a,
                                         unsigned int b0, unsigned int b1){
    asm volatile("mma.sync.aligned.m16n8k16.row.col.f32.bf16.bf16.f32 "
        "{%0,%1,%2,%3}, {%4,%5,%6,%7}, {%8,%9}, {%0,%1,%2,%3};"
        : "+f"(d[0]), "+f"(d[1]), "+f"(d[2]), "+f"(d[3])
        : "r"(a[0]), "r"(a[1]), "r"(a[2]), "r"(a[3]), "r"(b0), "r"(b1));
}
__device__ __forceinline__ unsigned packsplit(float a, float b, unsigned &lo){
    __nv_bfloat162 h = __floats2bfloat162_rn(a, b);
    float ra = a - __bfloat162float(h.x);
    float rb = b - __bfloat162float(h.y);
    __nv_bfloat162 l2 = __floats2bfloat162_rn(ra, rb);
    lo = *(unsigned*)&l2;
    return *(unsigned*)&h;
}

// ---------------- device scratch ----------------
#define BCL (Bb*Cc*LL)
__device__ float2 g_mif [BCL];
__device__ float2 g_mib [BCL];
__device__ float  g_sbv [BCL];
__device__ float  g_tokp[8][BCL];   // tok partials [type*4 + kq][b][l][c]
__device__ float  g_ns  [BCL];
__device__ float2 g_md  [2*Bb*LL];
__device__ float  g_pacc[2*Bb*LL*Cc];
__device__ float4 g_cellA[Bb*Cc*NCELL*NCELL];
__device__ float  g_cellM[Bb*NCELL*NCELL];
// bf16-split precomputes
__device__ bf16 g_whT[2*4096*64];       // [type][ck][d]
__device__ bf16 g_wlT[2*4096*64];
__device__ bf16 g_tokfh[Bb*LL*64];
__device__ bf16 g_tokfl[Bb*LL*64];
__device__ bf16 g_tokbTh[Bb*64*LLP];
__device__ bf16 g_tokbTl[Bb*64*LLP];
__device__ bf16 g_vh[Bb*LLP*64];
__device__ bf16 g_vl[Bb*LLP*64];

// ---------------- Kernel 1a: per-cell raw moments ----------------
__global__ __launch_bounds__(256)
void k_cells(const float* __restrict__ x, const float* __restrict__ mask)
{
    int idx = blockIdx.x * 256 + threadIdx.x;
    int cj = idx & 63;
    int ci = (idx >> 6) & 63;
    int c  = (idx >> 12) & 63;
    int b  = idx >> 18;

    const float* xp = x    + (((size_t)b * Cc + c) * Hh + ci * 4) * Ww + cj * 4;
    const float* mp = mask + ((size_t)b * HW + ci * 4 * Ww) + cj * 4;

    float s1 = 0.f, s2 = 0.f, sm1 = 0.f, sm2 = 0.f, ms = 0.f;
    #pragma unroll
    for (int r = 0; r < 4; r++) {
        float4 xv = *(const float4*)(xp + r * Ww);
        float4 mv = *(const float4*)(mp + r * Ww);
        float vv[4] = {xv.x, xv.y, xv.z, xv.w};
        float mm[4] = {mv.x, mv.y, mv.z, mv.w};
        #pragma unroll
        for (int k = 0; k < 4; k++) {
            float v = vv[k], m = mm[k];
            s1 += v; s2 += v * v;
            sm1 += m * v; sm2 += m * v * v;
            ms += m;
        }
    }
    g_cellA[idx] = make_float4(s1, s2, sm1, sm2);
    if (c == 0) g_cellM[b * (NCELL*NCELL) + ci * NCELL + cj] = ms;
}

// ---------------- Kernel 1b: patch stats from 4 cells ----------------
__global__ __launch_bounds__(256)
void k_pstats()
{
    int idx = blockIdx.x * 256 + threadIdx.x;
    if (idx >= Bb * Cc * LL) return;
    int l  = idx % LL;
    int bc = idx / LL;
    int lh = l / NUMS, lw = l - lh * NUMS;
    int b  = bc >> 6;

    const float4* ca = g_cellA + (size_t)bc * (NCELL*NCELL);
    const float*  cm = g_cellM + (size_t)b * (NCELL*NCELL);
    int c00 = lh * NCELL + lw;

    float4 a0 = ca[c00],         a1 = ca[c00 + 1];
    float4 a2 = ca[c00 + NCELL], a3 = ca[c00 + NCELL + 1];
    float msum = cm[c00] + cm[c00 + 1] + cm[c00 + NCELL] + cm[c00 + NCELL + 1];

    float s1  = a0.x + a1.x + a2.x + a3.x;
    float s2  = a0.y + a1.y + a2.y + a3.y;
    float sm1 = a0.z + a1.z + a2.z + a3.z;
    float sm2 = a0.w + a1.w + a2.w + a3.w;

    float numf = msum;
    float numb = 64.0f - msum;
    float mf = sm1 / (numf + EPSf);
    float vf = (sm2 - 2.f * mf * sm1 + mf * mf * numf) / (numf + EPSf);
    float sb1 = s1 - sm1, sb2 = s2 - sm2;
    float mb = sb1 / (numb + EPSf);
    float vb = (sb2 - 2.f * mb * sb1 + mb * mb * numb) / (numb + EPSf);

    g_mif[idx] = make_float2(mf, 1.0f / vf);
    g_mib[idx] = make_float2(mb, 1.0f / vb);
    int c = bc & 63;
    g_sbv[((size_t)b * LL + l) * Cc + c] = vb;
}

// ---------------- Kernel 1c: W -> transposed bf16 split ----------------
__global__ __launch_bounds__(256)
void k_wsplit(const float* __restrict__ wf, const float* __restrict__ wb)
{
    int type = blockIdx.y;
    int ck0  = blockIdx.x * 64;
    const float* w = type ? wb : wf;
    __shared__ float tile[64][65];
    int t = threadIdx.x;
    int d = t >> 2, q = t & 3;
    #pragma unroll
    for (int i = 0; i < 4; i++) {
        float4 v = *(const float4*)&w[(size_t)d * 4096 + ck0 + q * 16 + i * 4];
        tile[q*16 + i*4 + 0][d] = v.x;
        tile[q*16 + i*4 + 1][d] = v.y;
        tile[q*16 + i*4 + 2][d] = v.z;
        tile[q*16 + i*4 + 3][d] = v.w;
    }
    __syncthreads();
    int ck = t >> 2, q2 = t & 3, d0 = q2 * 16;
    bf16 hv[16], lv[16];
    #pragma unroll
    for (int j = 0; j < 16; j++) {
        float v = tile[ck][d0 + j];
        bf16 h = __float2bfloat16(v);
        hv[j] = h;
        lv[j] = __float2bfloat16(v - __bfloat162float(h));
    }
    size_t o = ((size_t)type * 4096 + ck0 + ck) * 64 + d0;
    *(uint4*)&g_whT[o]     = *(uint4*)&hv[0];
    *(uint4*)&g_whT[o + 8] = *(uint4*)&hv[8];
    *(uint4*)&g_wlT[o]     = *(uint4*)&lv[0];
    *(uint4*)&g_wlT[o + 8] = *(uint4*)&lv[8];
}

// ---------------- Kernel 2: token GEMM via mma.sync, K split 4-ways ----------------
// grid (63, Bb, 8): z = type*4 + kq. Each block: 64L x 64D x 1024K (32 phases).
__global__ __launch_bounds__(128)
void k_gemm(const float* __restrict__ x, const float* __restrict__ mask)
{
    int tile  = blockIdx.x;
    int b     = blockIdx.y;
    int type  = blockIdx.z >> 2;
    int kq    = blockIdx.z & 3;
    const float2* g_mi = type ? g_mib : g_mif;
    float* g_tk = g_tokp[blockIdx.z];

    int l0 = tile * 64;
    int t  = threadIdx.x;
    int lane = t & 31, warp = t >> 5;

    __shared__ __align__(16) bf16 Ah[64][40];
    __shared__ __align__(16) bf16 Al[64][40];
    __shared__ __align__(16) bf16 Wh[32][72];
    __shared__ __align__(16) bf16 Wl[32][72];

    int al_  = t >> 1;
    int ksel = t & 1;
    int lgl = l0 + al_;
    int lg  = (lgl < LL) ? lgl : (LL - 1);
    int lh = lg / NUMS, lw = lg - lh * NUMS;

    unsigned int msk[2];
    {
        const float* mp = mask + (size_t)b * HW + (lh * 4) * Ww + lw * 4;
        #pragma unroll
        for (int sub = 0; sub < 2; sub++) {
            unsigned int bits = 0;
            #pragma unroll
            for (int rr = 0; rr < 2; rr++) {
                int prow = sub * 4 + ksel * 2 + rr;
                float4 a = *(const float4*)(mp + prow * Ww);
                float4 bq = *(const float4*)(mp + prow * Ww + 4);
                float mv[8] = {a.x,a.y,a.z,a.w,bq.x,bq.y,bq.z,bq.w};
                #pragma unroll
                for (int kc = 0; kc < 8; kc++) {
                    bool on = mv[kc] > 0.5f;
                    if (type) on = !on;
                    bits |= (on ? 1u : 0u) << (rr * 8 + kc);
                }
            }
            msk[sub] = bits;
        }
    }

    int wrow = t >> 2, wq = t & 3;
    int c0 = kq * 16;

    float acc[8][4];
    #pragma unroll
    for (int i = 0; i < 8; i++)
        #pragma unroll
        for (int j = 0; j < 4; j++) acc[i][j] = 0.f;

    unsigned int aaddr_h[2], aaddr_l[2];
    unsigned int baddr_h[2][4], baddr_l[2][4];
    {
        int arow = warp * 16 + (lane & 15);
        int acol = (lane >> 4) << 3;
        int brow = lane & 15;
        int bcol = (lane >> 4) << 3;
        #pragma unroll
        for (int ks = 0; ks < 2; ks++) {
            aaddr_h[ks] = smaddr(&Ah[arow][ks * 16 + acol]);
            aaddr_l[ks] = smaddr(&Al[arow][ks * 16 + acol]);
            #pragma unroll
            for (int nb2 = 0; nb2 < 4; nb2++) {
                baddr_h[ks][nb2] = smaddr(&Wh[ks * 16 + brow][nb2 * 16 + bcol]);
                baddr_l[ks][nb2] = smaddr(&Wl[ks * 16 + brow][nb2 * 16 + bcol]);
            }
        }
    }

    for (int p = 0; p < 32; p++) {
        int c = c0 + (p >> 1), sub = p & 1;
        // ---- stage A (fma-form select, paired cvts, 32-bit STS) ----
        {
            const float* xp = x + (((size_t)b * Cc + c) * Hh + lh * 4 + sub * 4 + ksel * 2) * Ww + lw * 4;
            float4 r0a = *(const float4*)xp;
            float4 r0b = *(const float4*)(xp + 4);
            float4 r1a = *(const float4*)(xp + Ww);
            float4 r1b = *(const float4*)(xp + Ww + 4);
            float2 mi = g_mi[((size_t)b * Cc + c) * LL + lg];
            float negmuis = -mi.x * mi.y;
            unsigned int bits = msk[sub];
            float xv[16] = {r0a.x,r0a.y,r0a.z,r0a.w, r0b.x,r0b.y,r0b.z,r0b.w,
                            r1a.x,r1a.y,r1a.z,r1a.w, r1b.x,r1b.y,r1b.z,r1b.w};
            int kb = ksel * 16;
            #pragma unroll
            for (int i = 0; i < 8; i++) {
                bool on0 = (bits >> (2*i)) & 1u;
                bool on1 = (bits >> (2*i+1)) & 1u;
                float v0 = on0 ? fmaf(xv[2*i],   mi.y, negmuis) : mi.x;
                float v1 = on1 ? fmaf(xv[2*i+1], mi.y, negmuis) : mi.x;
                __nv_bfloat162 h2 = __floats2bfloat162_rn(v0, v1);
                float2 hf = __bfloat1622float2(h2);
                __nv_bfloat162 l2 = __floats2bfloat162_rn(v0 - hf.x, v1 - hf.y);
                *(unsigned*)&Ah[al_][kb + 2*i] = *(unsigned*)&h2;
                *(unsigned*)&Al[al_][kb + 2*i] = *(unsigned*)&l2;
            }
        }
        // ---- stage W (copy precomputed bf16) ----
        {
            size_t o = ((size_t)type * 4096 + c * 64 + sub * 32 + wrow) * 64 + wq * 16;
            uint4 h0 = *(const uint4*)&g_whT[o];
            uint4 h1 = *(const uint4*)&g_whT[o + 8];
            uint4 l0v = *(const uint4*)&g_wlT[o];
            uint4 l1v = *(const uint4*)&g_wlT[o + 8];
            *(uint4*)&Wh[wrow][wq * 16]     = h0;
            *(uint4*)&Wh[wrow][wq * 16 + 8] = h1;
            *(uint4*)&Wl[wrow][wq * 16]     = l0v;
            *(uint4*)&Wl[wrow][wq * 16 + 8] = l1v;
        }
        __syncthreads();

        #pragma unroll
        for (int ks = 0; ks < 2; ks++) {
            unsigned int ah[4], alr[4];
            ldsm4(ah,  aaddr_h[ks]);
            ldsm4(alr, aaddr_l[ks]);
            #pragma unroll
            for (int nb2 = 0; nb2 < 4; nb2++) {
                unsigned int bh[4], blr[4];
                ldsm4t(bh,  baddr_h[ks][nb2]);
                ldsm4t(blr, baddr_l[ks][nb2]);
                mma16816(acc[nb2*2],     ah,  bh[0],  bh[1]);
                mma16816(acc[nb2*2 + 1], ah,  bh[2],  bh[3]);
                mma16816(acc[nb2*2],     ah,  blr[0], blr[1]);
                mma16816(acc[nb2*2 + 1], ah,  blr[2], blr[3]);
                mma16816(acc[nb2*2],     alr, bh[0],  bh[1]);
                mma16816(acc[nb2*2 + 1], alr, bh[2],  bh[3]);
            }
        }
        __syncthreads();
    }

    int grp = lane >> 2, tig = lane & 3;
    #pragma unroll
    for (int nb = 0; nb < 8; nb++) {
        int d = nb * 8 + tig * 2;
        int lr0 = l0 + warp * 16 + grp;
        if (lr0 < LL)
            *(float2*)(g_tk + ((size_t)b * LL + lr0) * Cc + d) = make_float2(acc[nb][0], acc[nb][1]);
        int lr1 = lr0 + 8;
        if (lr1 < LL)
            *(float2*)(g_tk + ((size_t)b * LL + lr1) * Cc + d) = make_float2(acc[nb][2], acc[nb][3]);
    }
}

// ---------------- Kernel 2b: merge 4 partials/type + emit bf16-split Q/K^T/V ----------------
__global__ __launch_bounds__(256)
void k_prep()
{
    int b  = blockIdx.y;
    int l0 = blockIdx.x * 64;
    int t  = threadIdx.x;
    __shared__ float tb[64][65];

    int r = t >> 2, q = t & 3, c0 = q * 16;
    int l = l0 + r;
    bool valid = l < LL;

    float tf[16], tbv[16], sv[16];
    if (valid) {
        size_t o = ((size_t)b * LL + l) * 64 + c0;
        #pragma unroll
        for (int i = 0; i < 16; i += 4) {
            float4 a0 = *(const float4*)&g_tokp[0][o + i];
            float4 a1 = *(const float4*)&g_tokp[1][o + i];
            float4 a2 = *(const float4*)&g_tokp[2][o + i];
            float4 a3 = *(const float4*)&g_tokp[3][o + i];
            tf[i]   = a0.x + a1.x + a2.x + a3.x;
            tf[i+1] = a0.y + a1.y + a2.y + a3.y;
            tf[i+2] = a0.z + a1.z + a2.z + a3.z;
            tf[i+3] = a0.w + a1.w + a2.w + a3.w;
            float4 b0 = *(const float4*)&g_tokp[4][o + i];
            float4 b1 = *(const float4*)&g_tokp[5][o + i];
            float4 b2 = *(const float4*)&g_tokp[6][o + i];
            float4 b3 = *(const float4*)&g_tokp[7][o + i];
            tbv[i]   = b0.x + b1.x + b2.x + b3.x;
            tbv[i+1] = b0.y + b1.y + b2.y + b3.y;
            tbv[i+2] = b0.z + b1.z + b2.z + b3.z;
            tbv[i+3] = b0.w + b1.w + b2.w + b3.w;
            float4 s = *(const float4*)&g_sbv[o + i];
            sv[i] = s.x; sv[i+1] = s.y; sv[i+2] = s.z; sv[i+3] = s.w;
        }
    } else {
        #pragma unroll
        for (int i = 0; i < 16; i++) { tf[i] = 0.f; tbv[i] = 0.f; sv[i] = 0.f; }
    }

    if (valid) {
        bf16 h[16], lo[16];
        #pragma unroll
        for (int i = 0; i < 16; i++) {
            bf16 hh = __float2bfloat16(tf[i]);
            h[i] = hh; lo[i] = __float2bfloat16(tf[i] - __bfloat162float(hh));
        }
        size_t o = ((size_t)b * LL + l) * 64 + c0;
        *(uint4*)&g_tokfh[o]     = *(uint4*)&h[0];
        *(uint4*)&g_tokfh[o + 8] = *(uint4*)&h[8];
        *(uint4*)&g_tokfl[o]     = *(uint4*)&lo[0];
        *(uint4*)&g_tokfl[o + 8] = *(uint4*)&lo[8];
    }
    {
        bf16 h[16], lo[16];
        #pragma unroll
        for (int i = 0; i < 16; i++) {
            bf16 hh = __float2bfloat16(sv[i]);
            h[i] = hh; lo[i] = __float2bfloat16(sv[i] - __bfloat162float(hh));
        }
        size_t o = ((size_t)b * LLP + l) * 64 + c0;
        *(uint4*)&g_vh[o]     = *(uint4*)&h[0];
        *(uint4*)&g_vh[o + 8] = *(uint4*)&h[8];
        *(uint4*)&g_vl[o]     = *(uint4*)&lo[0];
        *(uint4*)&g_vl[o + 8] = *(uint4*)&lo[8];
    }
    #pragma unroll
    for (int i = 0; i < 16; i++) tb[r][c0 + i] = tbv[i];
    __syncthreads();

    int c = t >> 2, lq = t & 3;
    bf16 h[16], lo[16];
    #pragma unroll
    for (int j = 0; j < 16; j++) {
        float v = tb[lq * 16 + j][c];
        bf16 hh = __float2bfloat16(v);
        h[j] = hh; lo[j] = __float2bfloat16(v - __bfloat162float(hh));
    }
    size_t o = ((size_t)b * 64 + c) * LLP + l0 + lq * 16;
    *(uint4*)&g_tokbTh[o]     = *(uint4*)&h[0];
    *(uint4*)&g_tokbTh[o + 8] = *(uint4*)&h[8];
    *(uint4*)&g_tokbTl[o]     = *(uint4*)&lo[0];
    *(uint4*)&g_tokbTl[o + 8] = *(uint4*)&lo[8];
}

// ---------------- Kernel 3: attention via mma.sync (FA pattern, unchanged) ----------------
__global__ __launch_bounds__(256)
void k_attn(const float* __restrict__ rpb)
{
    int b = blockIdx.y, s = blockIdx.z;
    int l0 = blockIdx.x * 128;
    int t = threadIdx.x;
    int lane = t & 31, warp = t >> 5;
    int grp = lane >> 2, tig = lane & 3;

    __shared__ __align__(16) char sbuf[36864];
    __shared__ int rpish[64];
    bf16 (*Qh)[72] = (bf16(*)[72])sbuf;
    bf16 (*Ql)[72] = (bf16(*)[72])(sbuf + 18432);
    bf16 (*Kh)[72] = (bf16(*)[72])sbuf;
    bf16 (*Kl)[72] = (bf16(*)[72])(sbuf + 9216);
    bf16 (*Vh)[72] = (bf16(*)[72])(sbuf + 18432);
    bf16 (*Vl)[72] = (bf16(*)[72])(sbuf + 27648);

    #pragma unroll
    for (int i = 0; i < 4; i++) {
        int chunk = t + i * 256;
        int row = chunk >> 3, off = (chunk & 7) * 8;
        int lr = min(l0 + row, LL - 1);
        *(uint4*)&Qh[row][off] = *(const uint4*)&g_tokfh[((size_t)b * LL + lr) * 64 + off];
        *(uint4*)&Ql[row][off] = *(const uint4*)&g_tokfl[((size_t)b * LL + lr) * 64 + off];
    }
    __syncthreads();
    unsigned qh[4][4], ql[4][4];
    {
        int ar = warp * 16 + (lane & 15), ac = (lane >> 4) * 8;
        #pragma unroll
        for (int ks = 0; ks < 4; ks++) {
            ldsm4(qh[ks], smaddr(&Qh[ar][ks * 16 + ac]));
            ldsm4(ql[ks], smaddr(&Ql[ar][ks * 16 + ac]));
        }
    }
    __syncthreads();

    int r0 = l0 + warp * 16 + grp;
    int r1 = r0 + 8;
    int lr0 = min(r0, LL - 1), lr1 = min(r1, LL - 1);
    int rc0, rc1;
    { int lh = lr0 / NUMS, lw = lr0 - lh * NUMS; rc0 = (lh + 62) * TBL_W + (lw + 62); }
    { int lh = lr1 / NUMS, lw = lr1 - lh * NUMS; rc1 = (lh + 62) * TBL_W + (lw + 62); }

    float acc_o[8][4];
    #pragma unroll
    for (int i = 0; i < 8; i++)
        #pragma unroll
        for (int j = 0; j < 4; j++) acc_o[i][j] = 0.f;
    float mrun0 = -1e30f, mrun1 = -1e30f, dr0 = 0.f, dr1 = 0.f;

    unsigned int khb, klb, vhb, vlb;
    {
        unsigned int base = (lane & 15) * 144 + (lane >> 4) * 16;
        khb = smaddr(Kh) + base; klb = smaddr(Kl) + base;
        vhb = smaddr(Vh) + base; vlb = smaddr(Vl) + base;
    }

    int NT = 31 + s;
    for (int tt = 0; tt < NT; tt++) {
        int m0 = (s ? 1984 : 0) + tt * 64;
        #pragma unroll
        for (int i = 0; i < 2; i++) {
            int chunk = t + i * 256;
            int row = chunk >> 3, off = (chunk & 7) * 8;
            *(uint4*)&Kh[row][off] = *(const uint4*)&g_tokbTh[((size_t)b * 64 + row) * LLP + m0 + off];
            *(uint4*)&Kl[row][off] = *(const uint4*)&g_tokbTl[((size_t)b * 64 + row) * LLP + m0 + off];
            *(uint4*)&Vh[row][off] = *(const uint4*)&g_vh[((size_t)b * LLP + m0 + row) * 64 + off];
            *(uint4*)&Vl[row][off] = *(const uint4*)&g_vl[((size_t)b * LLP + m0 + row) * 64 + off];
        }
        if (t < 64) {
            int m = m0 + t;
            if (m < LL) { int mh = m / NUMS; rpish[t] = mh * TBL_W + (m - mh * NUMS); }
            else rpish[t] = -1;
        }
        __syncthreads();

        float accs[8][4];
        #pragma unroll
        for (int i = 0; i < 8; i++)
            #pragma unroll
            for (int j = 0; j < 4; j++) accs[i][j] = 0.f;
        #pragma unroll
        for (int ks = 0; ks < 4; ks++) {
            #pragma unroll
            for (int nb2 = 0; nb2 < 4; nb2++) {
                unsigned int bh[4], bl[4];
                ldsm4t(bh, khb + ks * 2304 + nb2 * 32);
                ldsm4t(bl, klb + ks * 2304 + nb2 * 32);
                mma16816(accs[nb2*2],     qh[ks], bh[0], bh[1]);
                mma16816(accs[nb2*2 + 1], qh[ks], bh[2], bh[3]);
                mma16816(accs[nb2*2],     qh[ks], bl[0], bl[1]);
                mma16816(accs[nb2*2 + 1], qh[ks], bl[2], bl[3]);
                mma16816(accs[nb2*2],     ql[ks], bh[0], bh[1]);
                mma16816(accs[nb2*2 + 1], ql[ks], bh[2], bh[3]);
            }
        }

        float tmax0 = -1e30f, tmax1 = -1e30f;
        #pragma unroll
        for (int nb = 0; nb < 8; nb++) {
            #pragma unroll
            for (int e = 0; e < 4; e++) {
                int off = rpish[nb * 8 + tig * 2 + (e & 1)];
                float bias = (off >= 0) ? __ldg(rpb + ((e < 2) ? rc0 : rc1) - off) : -1e30f;
                float v = accs[nb][e] + bias;
                accs[nb][e] = v;
                if (e < 2) tmax0 = fmaxf(tmax0, v); else tmax1 = fmaxf(tmax1, v);
            }
        }
        tmax0 = fmaxf(tmax0, __shfl_xor_sync(0xffffffff, tmax0, 1));
        tmax0 = fmaxf(tmax0, __shfl_xor_sync(0xffffffff, tmax0, 2));
        tmax1 = fmaxf(tmax1, __shfl_xor_sync(0xffffffff, tmax1, 1));
        tmax1 = fmaxf(tmax1, __shfl_xor_sync(0xffffffff, tmax1, 2));

        float nm0 = fmaxf(mrun0, tmax0), nm1 = fmaxf(mrun1, tmax1);
        float sc0 = __expf(mrun0 - nm0), sc1 = __expf(mrun1 - nm1);
        dr0 *= sc0; dr1 *= sc1;
        mrun0 = nm0; mrun1 = nm1;
        #pragma unroll
        for (int nb = 0; nb < 8; nb++) {
            acc_o[nb][0] *= sc0; acc_o[nb][1] *= sc0;
            acc_o[nb][2] *= sc1; acc_o[nb][3] *= sc1;
        }
        #pragma unroll
        for (int nb = 0; nb < 8; nb++) {
            float p0 = __expf(accs[nb][0] - nm0);
            float p1 = __expf(accs[nb][1] - nm0);
            float p2 = __expf(accs[nb][2] - nm1);
            float p3 = __expf(accs[nb][3] - nm1);
            accs[nb][0] = p0; accs[nb][1] = p1; accs[nb][2] = p2; accs[nb][3] = p3;
            dr0 += p0 + p1; dr1 += p2 + p3;
        }

        #pragma unroll
        for (int ks = 0; ks < 4; ks++) {
            unsigned ph[4], pl[4];
            ph[0] = packsplit(accs[2*ks][0],   accs[2*ks][1],   pl[0]);
            ph[1] = packsplit(accs[2*ks][2],   accs[2*ks][3],   pl[1]);
            ph[2] = packsplit(accs[2*ks+1][0], accs[2*ks+1][1], pl[2]);
            ph[3] = packsplit(accs[2*ks+1][2], accs[2*ks+1][3], pl[3]);
            #pragma unroll
            for (int nb2 = 0; nb2 < 4; nb2++) {
                unsigned int vh[4], vl[4];
                ldsm4t(vh, vhb + ks * 2304 + nb2 * 32);
                ldsm4t(vl, vlb + ks * 2304 + nb2 * 32);
                mma16816(acc_o[nb2*2],     ph, vh[0], vh[1]);
                mma16816(acc_o[nb2*2 + 1], ph, vh[2], vh[3]);
                mma16816(acc_o[nb2*2],     ph, vl[0], vl[1]);
                mma16816(acc_o[nb2*2 + 1], ph, vl[2], vl[3]);
                mma16816(acc_o[nb2*2],     pl, vh[0], vh[1]);
                mma16816(acc_o[nb2*2 + 1], pl, vh[2], vh[3]);
            }
        }
        __syncthreads();
    }

    dr0 += __shfl_xor_sync(0xffffffff, dr0, 1);
    dr0 += __shfl_xor_sync(0xffffffff, dr0, 2);
    dr1 += __shfl_xor_sync(0xffffffff, dr1, 1);
    dr1 += __shfl_xor_sync(0xffffffff, dr1, 2);

    if (r0 < LL) {
        float* dst = g_pacc + (((size_t)s * Bb + b) * LL + r0) * Cc;
        #pragma unroll
        for (int nb = 0; nb < 8; nb++)
            *(float2*)(dst + nb * 8 + tig * 2) = make_float2(acc_o[nb][0], acc_o[nb][1]);
        if (tig == 0) g_md[((size_t)s * Bb + b) * LL + r0] = make_float2(mrun0, dr0);
    }
    if (r1 < LL) {
        float* dst = g_pacc + (((size_t)s * Bb + b) * LL + r1) * Cc;
        #pragma unroll
        for (int nb = 0; nb < 8; nb++)
            *(float2*)(dst + nb * 8 + tig * 2) = make_float2(acc_o[nb][2], acc_o[nb][3]);
        if (tig == 0) g_md[((size_t)s * Bb + b) * LL + r1] = make_float2(mrun1, dr1);
    }
}

// ---------------- Kernel 3b: combine m-splits -> g_ns ----------------
__global__ __launch_bounds__(256)
void k_combine()
{
    int idx = blockIdx.x * 256 + threadIdx.x;
    if (idx >= Bb * LL * Cc) return;
    int c   = idx & 63;
    int row = idx >> 6;
    int l   = row % LL;
    int b   = row / LL;
    float2 md0 = g_md[(size_t)b * LL + l];
    float2 md1 = g_md[((size_t)Bb + b) * LL + l];
    float M  = fmaxf(md0.x, md1.x);
    float w0 = __expf(md0.x - M);
    float w1 = __expf(md1.x - M);
    float a0 = g_pacc[((size_t)b * LL + l) * Cc + c];
    float a1 = g_pacc[(((size_t)Bb + b) * LL + l) * Cc + c];
    g_ns[((size_t)b * Cc + c) * LL + l] =
        (w0 * a0 + w1 * a1) / (w0 * md0.y + w1 * md1.y);
}

// ---------------- Kernel 4: fold + epilogue ----------------
__global__ __launch_bounds__(256)
void k_epilogue(const float* __restrict__ x, const float* __restrict__ mask,
                const float* __restrict__ fg_g, const float* __restrict__ fg_b,
                const float* __restrict__ bg_g, const float* __restrict__ bg_b,
                float* __restrict__ out)
{
    int tid = blockIdx.x * 256 + threadIdx.x;
    int idx = tid * 4;
    int w0 = idx & 255;
    int h  = (idx >> 8) & 255;
    int c  = (idx >> 16) & 63;
    int b  = idx >> 22;
    int q  = w0 >> 2;

    float4 mv = *(const float4*)(mask + (size_t)b * HW + h * Ww + w0);
    float4 xv = *(const float4*)(x + idx);

    float bgG = 1.0f + bg_g[c], bgB = bg_b[c];
    float fgG = 1.0f + fg_g[c], fgB = fg_b[c];

    int ih_hi = h >> 2;  int ih_lo = ih_hi - 1;
    bool vh_hi = (ih_hi <= NUMS - 1), vh_lo = (ih_lo >= 0);
    int iw_hi = q;       int iw_lo = q - 1;
    bool vw_hi = (iw_hi <= NUMS - 1), vw_lo = (iw_lo >= 0);

    float m[4]  = {mv.x, mv.y, mv.z, mv.w};
    float xs[4] = {xv.x, xv.y, xv.z, xv.w};
    float xm[4], inm[4];
    #pragma unroll
    for (int p = 0; p < 4; p++) { inm[p] = 1.0f - m[p]; xm[p] = xs[p] * m[p]; }

    float sum[4] = {0.f, 0.f, 0.f, 0.f};
    size_t base = ((size_t)b * Cc + c) * LL;

    int ihv[2] = {ih_lo, ih_hi};  bool vav[2] = {vh_lo, vh_hi};
    int iwv[2] = {iw_lo, iw_hi};  bool vev[2] = {vw_lo, vw_hi};
    #pragma unroll
    for (int a = 0; a < 2; a++) {
        #pragma unroll
        for (int e = 0; e < 2; e++) {
            if (vav[a] && vev[e]) {
                int lp = ihv[a] * NUMS + iwv[e];
                float2 mi = g_mif[base + lp];
                float ns  = g_ns [base + lp];
                #pragma unroll
                for (int p = 0; p < 4; p++) {
                    float inf_ = (xm[p] - mi.x) * mi.y * m[p] + mi.x * inm[p];
                    sum[p] += inf_ * ns + ns;
                }
            }
        }
    }
    int cnt = ((int)vh_hi + (int)vh_lo) * ((int)vw_hi + (int)vw_lo);
    float invc = (cnt == 4) ? 0.25f : ((cnt == 2) ? 0.5f : 1.0f);

    float r[4];
    #pragma unroll
    for (int p = 0; p < 4; p++) {
        float ubg = (xs[p] * inm[p] * bgG + bgB) * inm[p];
        float val = (sum[p] * invc) * fgG + fgB;
        r[p] = val * m[p] + ubg;
    }
    *(float4*)(out + idx) = make_float4(r[0], r[1], r[2], r[3]);
}

// ---------------- launch ----------------
extern "C" void kernel_launch(void* const* d_in, const int* in_sizes, int n_in,
                              void* d_out, int out_size)
{
    const float* x       = (const float*)d_in[0];
    const float* mask    = (const float*)d_in[1];
    const float* fg_g    = (const float*)d_in[2];
    const float* fg_b    = (const float*)d_in[3];
    const float* bg_g    = (const float*)d_in[4];
    const float* bg_b    = (const float*)d_in[5];
    const float* w_fore  = (const float*)d_in[6];
    const float* w_back  = (const float*)d_in[7];
    const float* rpb     = (const float*)d_in[8];
    float* out = (float*)d_out;

    k_cells<<<(Bb * Cc * NCELL * NCELL) / 256, 256>>>(x, mask);
    k_pstats<<<(Bb * Cc * LL + 255) / 256, 256>>>();
    k_wsplit<<<dim3(64, 2), 256>>>(w_fore, w_back);
    k_gemm<<<dim3(63, Bb, 8), 128>>>(x, mask);
    k_prep<<<dim3(63, Bb), 256>>>();
    k_attn<<<dim3(32, Bb, 2), 256>>>(rpb);
    k_combine<<<(Bb * LL * Cc + 255) / 256, 256>>>();
    k_epilogue<<<(Bb * Cc * HW) / (256 * 4), 256>>>(x, mask, fg_g, fg_b, bg_g, bg_b, out);
}

// round 14
// speedup vs baseline: 1.0798x; 1.0798x over previous
#include <cuda_runtime.h>
#include <cuda_bf16.h>

#define Bb 2
#define Cc 64
#define Hh 256
#define Ww 256
#define HW (Hh*Ww)
#define NUMS 63
#define LL (NUMS*NUMS)          // 3969
#define LLP 4032
#define K2 64
#define EPSf 1e-5f
#define TBL_W (2*NUMS-1)        // 125
#define NCELL 64

typedef unsigned long long ull;
typedef __nv_bfloat16 bf16;

__device__ __forceinline__ unsigned int smaddr(const void* p){
    return (unsigned int)__cvta_generic_to_shared(p);
}
__device__ __forceinline__ void ldsm4(unsigned int* r, unsigned int addr){
    asm volatile("ldmatrix.sync.aligned.m8n8.x4.shared.b16 {%0,%1,%2,%3}, [%4];"
        : "=r"(r[0]), "=r"(r[1]), "=r"(r[2]), "=r"(r[3]) : "r"(addr));
}
__device__ __forceinline__ void ldsm4t(unsigned int* r, unsigned int addr){
    asm volatile("ldmatrix.sync.aligned.m8n8.x4.trans.shared.b16 {%0,%1,%2,%3}, [%4];"
        : "=r"(r[0]), "=r"(r[1]), "=r"(r[2]), "=r"(r[3]) : "r"(addr));
}
__device__ __forceinline__ void mma16816(float* d, const unsigned int* a,
                                         unsigned int b0, unsigned int b1){
    asm volatile("mma.sync.aligned.m16n8k16.row.col.f32.bf16.bf16.f32 "
        "{%0,%1,%2,%3}, {%4,%5,%6,%7}, {%8,%9}, {%0,%1,%2,%3};"
        : "+f"(d[0]), "+f"(d[1]), "+f"(d[2]), "+f"(d[3])
        : "r"(a[0]), "r"(a[1]), "r"(a[2]), "r"(a[3]), "r"(b0), "r"(b1));
}
__device__ __forceinline__ unsigned packsplit(float a, float b, unsigned &lo){
    __nv_bfloat162 h = __floats2bfloat162_rn(a, b);
    float ra = a - __bfloat162float(h.x);
    float rb = b - __bfloat162float(h.y);
    __nv_bfloat162 l2 = __floats2bfloat162_rn(ra, rb);
    lo = *(unsigned*)&l2;
    return *(unsigned*)&h;
}

// ---------------- device scratch ----------------
#define BCL (Bb*Cc*LL)
__device__ float2 g_mif [BCL];
__device__ float2 g_mib [BCL];
__device__ float  g_sbv [BCL];
__device__ float  g_tokp[8][BCL];   // tok partials [type*4 + kq][b][l][c]
__device__ float  g_ns  [BCL];
__device__ float2 g_md  [2*Bb*LL];
__device__ float  g_pacc[2*Bb*LL*Cc];
__device__ float4 g_cellA[Bb*Cc*NCELL*NCELL];
__device__ float  g_cellM[Bb*NCELL*NCELL];
__device__ bf16 g_whT[2*4096*64];
__device__ bf16 g_wlT[2*4096*64];
__device__ bf16 g_tokfh[Bb*LL*64];
__device__ bf16 g_tokfl[Bb*LL*64];
__device__ bf16 g_tokbTh[Bb*64*LLP];
__device__ bf16 g_tokbTl[Bb*64*LLP];
__device__ bf16 g_vh[Bb*LLP*64];
__device__ bf16 g_vl[Bb*LLP*64];

// ---------------- Kernel 1a: per-cell raw moments ----------------
__global__ __launch_bounds__(256)
void k_cells(const float* __restrict__ x, const float* __restrict__ mask)
{
    int idx = blockIdx.x * 256 + threadIdx.x;
    int cj = idx & 63;
    int ci = (idx >> 6) & 63;
    int c  = (idx >> 12) & 63;
    int b  = idx >> 18;

    const float* xp = x    + (((size_t)b * Cc + c) * Hh + ci * 4) * Ww + cj * 4;
    const float* mp = mask + ((size_t)b * HW + ci * 4 * Ww) + cj * 4;

    float s1 = 0.f, s2 = 0.f, sm1 = 0.f, sm2 = 0.f, ms = 0.f;
    #pragma unroll
    for (int r = 0; r < 4; r++) {
        float4 xv = *(const float4*)(xp + r * Ww);
        float4 mv = *(const float4*)(mp + r * Ww);
        float vv[4] = {xv.x, xv.y, xv.z, xv.w};
        float mm[4] = {mv.x, mv.y, mv.z, mv.w};
        #pragma unroll
        for (int k = 0; k < 4; k++) {
            float v = vv[k], m = mm[k];
            s1 += v; s2 += v * v;
            sm1 += m * v; sm2 += m * v * v;
            ms += m;
        }
    }
    g_cellA[idx] = make_float4(s1, s2, sm1, sm2);
    if (c == 0) g_cellM[b * (NCELL*NCELL) + ci * NCELL + cj] = ms;
}

// ---------------- Kernel 1b: patch stats from 4 cells ----------------
__global__ __launch_bounds__(256)
void k_pstats()
{
    int idx = blockIdx.x * 256 + threadIdx.x;
    if (idx >= Bb * Cc * LL) return;
    int l  = idx % LL;
    int bc = idx / LL;
    int lh = l / NUMS, lw = l - lh * NUMS;
    int b  = bc >> 6;

    const float4* ca = g_cellA + (size_t)bc * (NCELL*NCELL);
    const float*  cm = g_cellM + (size_t)b * (NCELL*NCELL);
    int c00 = lh * NCELL + lw;

    float4 a0 = ca[c00],         a1 = ca[c00 + 1];
    float4 a2 = ca[c00 + NCELL], a3 = ca[c00 + NCELL + 1];
    float msum = cm[c00] + cm[c00 + 1] + cm[c00 + NCELL] + cm[c00 + NCELL + 1];

    float s1  = a0.x + a1.x + a2.x + a3.x;
    float s2  = a0.y + a1.y + a2.y + a3.y;
    float sm1 = a0.z + a1.z + a2.z + a3.z;
    float sm2 = a0.w + a1.w + a2.w + a3.w;

    float numf = msum;
    float numb = 64.0f - msum;
    float mf = sm1 / (numf + EPSf);
    float vf = (sm2 - 2.f * mf * sm1 + mf * mf * numf) / (numf + EPSf);
    float sb1 = s1 - sm1, sb2 = s2 - sm2;
    float mb = sb1 / (numb + EPSf);
    float vb = (sb2 - 2.f * mb * sb1 + mb * mb * numb) / (numb + EPSf);

    g_mif[idx] = make_float2(mf, 1.0f / vf);
    g_mib[idx] = make_float2(mb, 1.0f / vb);
    int c = bc & 63;
    g_sbv[((size_t)b * LL + l) * Cc + c] = vb;
}

// ---------------- Kernel 1c: W -> transposed bf16 split ----------------
__global__ __launch_bounds__(256)
void k_wsplit(const float* __restrict__ wf, const float* __restrict__ wb)
{
    int type = blockIdx.y;
    int ck0  = blockIdx.x * 64;
    const float* w = type ? wb : wf;
    __shared__ float tile[64][65];
    int t = threadIdx.x;
    int d = t >> 2, q = t & 3;
    #pragma unroll
    for (int i = 0; i < 4; i++) {
        float4 v = *(const float4*)&w[(size_t)d * 4096 + ck0 + q * 16 + i * 4];
        tile[q*16 + i*4 + 0][d] = v.x;
        tile[q*16 + i*4 + 1][d] = v.y;
        tile[q*16 + i*4 + 2][d] = v.z;
        tile[q*16 + i*4 + 3][d] = v.w;
    }
    __syncthreads();
    int ck = t >> 2, q2 = t & 3, d0 = q2 * 16;
    bf16 hv[16], lv[16];
    #pragma unroll
    for (int j = 0; j < 16; j++) {
        float v = tile[ck][d0 + j];
        bf16 h = __float2bfloat16(v);
        hv[j] = h;
        lv[j] = __float2bfloat16(v - __bfloat162float(h));
    }
    size_t o = ((size_t)type * 4096 + ck0 + ck) * 64 + d0;
    *(uint4*)&g_whT[o]     = *(uint4*)&hv[0];
    *(uint4*)&g_whT[o + 8] = *(uint4*)&hv[8];
    *(uint4*)&g_wlT[o]     = *(uint4*)&lv[0];
    *(uint4*)&g_wlT[o + 8] = *(uint4*)&lv[8];
}

// ---------------- Kernel 2: token GEMM, 128L/block, warp owns 32 M-rows ----------------
// grid (32, Bb, 8): z = type*4 + kq. Block: 128L x 64D x 1024K (32 phases).
__global__ __launch_bounds__(128)
void k_gemm(const float* __restrict__ x, const float* __restrict__ mask)
{
    int tile  = blockIdx.x;              // 0..31 (l-tiles of 128)
    int b     = blockIdx.y;
    int type  = blockIdx.z >> 2;
    int kq    = blockIdx.z & 3;
    const float2* g_mi = type ? g_mib : g_mif;
    float* g_tk = g_tokp[blockIdx.z];

    int l0 = tile * 128;
    int t  = threadIdx.x;
    int lane = t & 31, warp = t >> 5;

    __shared__ __align__(16) bf16 Ah[128][40];
    __shared__ __align__(16) bf16 Al[128][40];
    __shared__ __align__(16) bf16 Wh[32][72];
    __shared__ __align__(16) bf16 Wl[32][72];

    // A staging: thread t builds row t (all 32 k per phase)
    int lgl = l0 + t;
    int lg  = (lgl < LL) ? lgl : (LL - 1);
    int lh = lg / NUMS, lw = lg - lh * NUMS;

    unsigned int mb0 = 0, mb1 = 0;
    {
        const float* mp = mask + (size_t)b * HW + (lh * 4) * Ww + lw * 4;
        #pragma unroll
        for (int r = 0; r < 8; r++) {
            float4 a = *(const float4*)(mp + r * Ww);
            float4 bq = *(const float4*)(mp + r * Ww + 4);
            float mv[8] = {a.x,a.y,a.z,a.w,bq.x,bq.y,bq.z,bq.w};
            unsigned int bits = 0;
            #pragma unroll
            for (int kw = 0; kw < 8; kw++) {
                bool on = mv[kw] > 0.5f;
                if (type) on = !on;
                bits |= (on ? 1u : 0u) << (((r & 3) * 8) + kw);
            }
            if (r < 4) mb0 |= bits; else mb1 |= bits;
        }
    }

    int wrow = t >> 2, wq = t & 3;
    int c0 = kq * 16;

    float acc[2][8][4];
    #pragma unroll
    for (int f = 0; f < 2; f++)
        #pragma unroll
        for (int i = 0; i < 8; i++)
            #pragma unroll
            for (int j = 0; j < 4; j++) acc[f][i][j] = 0.f;

    unsigned int aaddr_h[2][2], aaddr_l[2][2];     // [frag][ks]
    unsigned int baddr_h[2][4], baddr_l[2][4];     // [ks][nb2]
    {
        int acol = (lane >> 4) << 3;
        int brow = lane & 15;
        int bcol = (lane >> 4) << 3;
        #pragma unroll
        for (int f = 0; f < 2; f++) {
            int arow = warp * 32 + f * 16 + (lane & 15);
            #pragma unroll
            for (int ks = 0; ks < 2; ks++) {
                aaddr_h[f][ks] = smaddr(&Ah[arow][ks * 16 + acol]);
                aaddr_l[f][ks] = smaddr(&Al[arow][ks * 16 + acol]);
            }
        }
        #pragma unroll
        for (int ks = 0; ks < 2; ks++)
            #pragma unroll
            for (int nb2 = 0; nb2 < 4; nb2++) {
                baddr_h[ks][nb2] = smaddr(&Wh[ks * 16 + brow][nb2 * 16 + bcol]);
                baddr_l[ks][nb2] = smaddr(&Wl[ks * 16 + brow][nb2 * 16 + bcol]);
            }
    }

    for (int p = 0; p < 32; p++) {
        int c = c0 + (p >> 1), sub = p & 1;
        // ---- stage A: full 32-k row per thread ----
        {
            const float* xp = x + (((size_t)b * Cc + c) * Hh + lh * 4 + sub * 4) * Ww + lw * 4;
            float2 mi = g_mi[((size_t)b * Cc + c) * LL + lg];
            float negmuis = -mi.x * mi.y;
            unsigned int bits = sub ? mb1 : mb0;
            #pragma unroll
            for (int r = 0; r < 4; r++) {
                float4 xa = *(const float4*)(xp + r * Ww);
                float4 xb = *(const float4*)(xp + r * Ww + 4);
                float xv[8] = {xa.x,xa.y,xa.z,xa.w, xb.x,xb.y,xb.z,xb.w};
                #pragma unroll
                for (int i = 0; i < 4; i++) {
                    bool on0 = (bits >> (r * 8 + 2*i)) & 1u;
                    bool on1 = (bits >> (r * 8 + 2*i + 1)) & 1u;
                    float v0 = on0 ? fmaf(xv[2*i],   mi.y, negmuis) : mi.x;
                    float v1 = on1 ? fmaf(xv[2*i+1], mi.y, negmuis) : mi.x;
                    __nv_bfloat162 h2 = __floats2bfloat162_rn(v0, v1);
                    float2 hf = __bfloat1622float2(h2);
                    __nv_bfloat162 l2 = __floats2bfloat162_rn(v0 - hf.x, v1 - hf.y);
                    *(unsigned*)&Ah[t][r * 8 + 2*i] = *(unsigned*)&h2;
                    *(unsigned*)&Al[t][r * 8 + 2*i] = *(unsigned*)&l2;
                }
            }
        }
        // ---- stage W ----
        {
            size_t o = ((size_t)type * 4096 + c * 64 + sub * 32 + wrow) * 64 + wq * 16;
            uint4 h0 = *(const uint4*)&g_whT[o];
            uint4 h1 = *(const uint4*)&g_whT[o + 8];
            uint4 l0v = *(const uint4*)&g_wlT[o];
            uint4 l1v = *(const uint4*)&g_wlT[o + 8];
            *(uint4*)&Wh[wrow][wq * 16]     = h0;
            *(uint4*)&Wh[wrow][wq * 16 + 8] = h1;
            *(uint4*)&Wl[wrow][wq * 16]     = l0v;
            *(uint4*)&Wl[wrow][wq * 16 + 8] = l1v;
        }
        __syncthreads();

        #pragma unroll
        for (int ks = 0; ks < 2; ks++) {
            unsigned int ah[2][4], alr[2][4];
            #pragma unroll
            for (int f = 0; f < 2; f++) {
                ldsm4(ah[f],  aaddr_h[f][ks]);
                ldsm4(alr[f], aaddr_l[f][ks]);
            }
            #pragma unroll
            for (int nb2 = 0; nb2 < 4; nb2++) {
                unsigned int bh[4], blr[4];
                ldsm4t(bh,  baddr_h[ks][nb2]);
                ldsm4t(blr, baddr_l[ks][nb2]);
                #pragma unroll
                for (int f = 0; f < 2; f++) {
                    mma16816(acc[f][nb2*2],     ah[f],  bh[0],  bh[1]);
                    mma16816(acc[f][nb2*2 + 1], ah[f],  bh[2],  bh[3]);
                    mma16816(acc[f][nb2*2],     ah[f],  blr[0], blr[1]);
                    mma16816(acc[f][nb2*2 + 1], ah[f],  blr[2], blr[3]);
                    mma16816(acc[f][nb2*2],     alr[f], bh[0],  bh[1]);
                    mma16816(acc[f][nb2*2 + 1], alr[f], bh[2],  bh[3]);
                }
            }
        }
        __syncthreads();
    }

    int grp = lane >> 2, tig = lane & 3;
    #pragma unroll
    for (int f = 0; f < 2; f++) {
        #pragma unroll
        for (int nb = 0; nb < 8; nb++) {
            int d = nb * 8 + tig * 2;
            int lr0 = l0 + warp * 32 + f * 16 + grp;
            if (lr0 < LL)
                *(float2*)(g_tk + ((size_t)b * LL + lr0) * Cc + d) = make_float2(acc[f][nb][0], acc[f][nb][1]);
            int lr1 = lr0 + 8;
            if (lr1 < LL)
                *(float2*)(g_tk + ((size_t)b * LL + lr1) * Cc + d) = make_float2(acc[f][nb][2], acc[f][nb][3]);
        }
    }
}

// ---------------- Kernel 2b: merge 4 partials/type + emit bf16-split Q/K^T/V ----------------
__global__ __launch_bounds__(256)
void k_prep()
{
    int b  = blockIdx.y;
    int l0 = blockIdx.x * 64;
    int t  = threadIdx.x;
    __shared__ float tb[64][65];

    int r = t >> 2, q = t & 3, c0 = q * 16;
    int l = l0 + r;
    bool valid = l < LL;

    float tf[16], tbv[16], sv[16];
    if (valid) {
        size_t o = ((size_t)b * LL + l) * 64 + c0;
        #pragma unroll
        for (int i = 0; i < 16; i += 4) {
            float4 a0 = *(const float4*)&g_tokp[0][o + i];
            float4 a1 = *(const float4*)&g_tokp[1][o + i];
            float4 a2 = *(const float4*)&g_tokp[2][o + i];
            float4 a3 = *(const float4*)&g_tokp[3][o + i];
            tf[i]   = a0.x + a1.x + a2.x + a3.x;
            tf[i+1] = a0.y + a1.y + a2.y + a3.y;
            tf[i+2] = a0.z + a1.z + a2.z + a3.z;
            tf[i+3] = a0.w + a1.w + a2.w + a3.w;
            float4 b0 = *(const float4*)&g_tokp[4][o + i];
            float4 b1 = *(const float4*)&g_tokp[5][o + i];
            float4 b2 = *(const float4*)&g_tokp[6][o + i];
            float4 b3 = *(const float4*)&g_tokp[7][o + i];
            tbv[i]   = b0.x + b1.x + b2.x + b3.x;
            tbv[i+1] = b0.y + b1.y + b2.y + b3.y;
            tbv[i+2] = b0.z + b1.z + b2.z + b3.z;
            tbv[i+3] = b0.w + b1.w + b2.w + b3.w;
            float4 s = *(const float4*)&g_sbv[o + i];
            sv[i] = s.x; sv[i+1] = s.y; sv[i+2] = s.z; sv[i+3] = s.w;
        }
    } else {
        #pragma unroll
        for (int i = 0; i < 16; i++) { tf[i] = 0.f; tbv[i] = 0.f; sv[i] = 0.f; }
    }

    if (valid) {
        bf16 h[16], lo[16];
        #pragma unroll
        for (int i = 0; i < 16; i++) {
            bf16 hh = __float2bfloat16(tf[i]);
            h[i] = hh; lo[i] = __float2bfloat16(tf[i] - __bfloat162float(hh));
        }
        size_t o = ((size_t)b * LL + l) * 64 + c0;
        *(uint4*)&g_tokfh[o]     = *(uint4*)&h[0];
        *(uint4*)&g_tokfh[o + 8] = *(uint4*)&h[8];
        *(uint4*)&g_tokfl[o]     = *(uint4*)&lo[0];
        *(uint4*)&g_tokfl[o + 8] = *(uint4*)&lo[8];
    }
    {
        bf16 h[16], lo[16];
        #pragma unroll
        for (int i = 0; i < 16; i++) {
            bf16 hh = __float2bfloat16(sv[i]);
            h[i] = hh; lo[i] = __float2bfloat16(sv[i] - __bfloat162float(hh));
        }
        size_t o = ((size_t)b * LLP + l) * 64 + c0;
        *(uint4*)&g_vh[o]     = *(uint4*)&h[0];
        *(uint4*)&g_vh[o + 8] = *(uint4*)&h[8];
        *(uint4*)&g_vl[o]     = *(uint4*)&lo[0];
        *(uint4*)&g_vl[o + 8] = *(uint4*)&lo[8];
    }
    #pragma unroll
    for (int i = 0; i < 16; i++) tb[r][c0 + i] = tbv[i];
    __syncthreads();

    int c = t >> 2, lq = t & 3;
    bf16 h[16], lo[16];
    #pragma unroll
    for (int j = 0; j < 16; j++) {
        float v = tb[lq * 16 + j][c];
        bf16 hh = __float2bfloat16(v);
        h[j] = hh; lo[j] = __float2bfloat16(v - __bfloat162float(hh));
    }
    size_t o = ((size_t)b * 64 + c) * LLP + l0 + lq * 16;
    *(uint4*)&g_tokbTh[o]     = *(uint4*)&h[0];
    *(uint4*)&g_tokbTh[o + 8] = *(uint4*)&h[8];
    *(uint4*)&g_tokbTl[o]     = *(uint4*)&lo[0];
    *(uint4*)&g_tokbTl[o + 8] = *(uint4*)&lo[8];
}

// ---------------- Kernel 3: attention via mma.sync (FA pattern, unchanged) ----------------
__global__ __launch_bounds__(256)
void k_attn(const float* __restrict__ rpb)
{
    int b = blockIdx.y, s = blockIdx.z;
    int l0 = blockIdx.x * 128;
    int t = threadIdx.x;
    int lane = t & 31, warp = t >> 5;
    int grp = lane >> 2, tig = lane & 3;

    __shared__ __align__(16) char sbuf[36864];
    __shared__ int rpish[64];
    bf16 (*Qh)[72] = (bf16(*)[72])sbuf;
    bf16 (*Ql)[72] = (bf16(*)[72])(sbuf + 18432);
    bf16 (*Kh)[72] = (bf16(*)[72])sbuf;
    bf16 (*Kl)[72] = (bf16(*)[72])(sbuf + 9216);
    bf16 (*Vh)[72] = (bf16(*)[72])(sbuf + 18432);
    bf16 (*Vl)[72] = (bf16(*)[72])(sbuf + 27648);

    #pragma unroll
    for (int i = 0; i < 4; i++) {
        int chunk = t + i * 256;
        int row = chunk >> 3, off = (chunk & 7) * 8;
        int lr = min(l0 + row, LL - 1);
        *(uint4*)&Qh[row][off] = *(const uint4*)&g_tokfh[((size_t)b * LL + lr) * 64 + off];
        *(uint4*)&Ql[row][off] = *(const uint4*)&g_tokfl[((size_t)b * LL + lr) * 64 + off];
    }
    __syncthreads();
    unsigned qh[4][4], ql[4][4];
    {
        int ar = warp * 16 + (lane & 15), ac = (lane >> 4) * 8;
        #pragma unroll
        for (int ks = 0; ks < 4; ks++) {
            ldsm4(qh[ks], smaddr(&Qh[ar][ks * 16 + ac]));
            ldsm4(ql[ks], smaddr(&Ql[ar][ks * 16 + ac]));
        }
    }
    __syncthreads();

    int r0 = l0 + warp * 16 + grp;
    int r1 = r0 + 8;
    int lr0 = min(r0, LL - 1), lr1 = min(r1, LL - 1);
    int rc0, rc1;
    { int lh = lr0 / NUMS, lw = lr0 - lh * NUMS; rc0 = (lh + 62) * TBL_W + (lw + 62); }
    { int lh = lr1 / NUMS, lw = lr1 - lh * NUMS; rc1 = (lh + 62) * TBL_W + (lw + 62); }

    float acc_o[8][4];
    #pragma unroll
    for (int i = 0; i < 8; i++)
        #pragma unroll
        for (int j = 0; j < 4; j++) acc_o[i][j] = 0.f;
    float mrun0 = -1e30f, mrun1 = -1e30f, dr0 = 0.f, dr1 = 0.f;

    unsigned int khb, klb, vhb, vlb;
    {
        unsigned int base = (lane & 15) * 144 + (lane >> 4) * 16;
        khb = smaddr(Kh) + base; klb = smaddr(Kl) + base;
        vhb = smaddr(Vh) + base; vlb = smaddr(Vl) + base;
    }

    int NT = 31 + s;
    for (int tt = 0; tt < NT; tt++) {
        int m0 = (s ? 1984 : 0) + tt * 64;
        #pragma unroll
        for (int i = 0; i < 2; i++) {
            int chunk = t + i * 256;
            int row = chunk >> 3, off = (chunk & 7) * 8;
            *(uint4*)&Kh[row][off] = *(const uint4*)&g_tokbTh[((size_t)b * 64 + row) * LLP + m0 + off];
            *(uint4*)&Kl[row][off] = *(const uint4*)&g_tokbTl[((size_t)b * 64 + row) * LLP + m0 + off];
            *(uint4*)&Vh[row][off] = *(const uint4*)&g_vh[((size_t)b * LLP + m0 + row) * 64 + off];
            *(uint4*)&Vl[row][off] = *(const uint4*)&g_vl[((size_t)b * LLP + m0 + row) * 64 + off];
        }
        if (t < 64) {
            int m = m0 + t;
            if (m < LL) { int mh = m / NUMS; rpish[t] = mh * TBL_W + (m - mh * NUMS); }
            else rpish[t] = -1;
        }
        __syncthreads();

        float accs[8][4];
        #pragma unroll
        for (int i = 0; i < 8; i++)
            #pragma unroll
            for (int j = 0; j < 4; j++) accs[i][j] = 0.f;
        #pragma unroll
        for (int ks = 0; ks < 4; ks++) {
            #pragma unroll
            for (int nb2 = 0; nb2 < 4; nb2++) {
                unsigned int bh[4], bl[4];
                ldsm4t(bh, khb + ks * 2304 + nb2 * 32);
                ldsm4t(bl, klb + ks * 2304 + nb2 * 32);
                mma16816(accs[nb2*2],     qh[ks], bh[0], bh[1]);
                mma16816(accs[nb2*2 + 1], qh[ks], bh[2], bh[3]);
                mma16816(accs[nb2*2],     qh[ks], bl[0], bl[1]);
                mma16816(accs[nb2*2 + 1], qh[ks], bl[2], bl[3]);
                mma16816(accs[nb2*2],     ql[ks], bh[0], bh[1]);
                mma16816(accs[nb2*2 + 1], ql[ks], bh[2], bh[3]);
            }
        }

        float tmax0 = -1e30f, tmax1 = -1e30f;
        #pragma unroll
        for (int nb = 0; nb < 8; nb++) {
            #pragma unroll
            for (int e = 0; e < 4; e++) {
                int off = rpish[nb * 8 + tig * 2 + (e & 1)];
                float bias = (off >= 0) ? __ldg(rpb + ((e < 2) ? rc0 : rc1) - off) : -1e30f;
                float v = accs[nb][e] + bias;
                accs[nb][e] = v;
                if (e < 2) tmax0 = fmaxf(tmax0, v); else tmax1 = fmaxf(tmax1, v);
            }
        }
        tmax0 = fmaxf(tmax0, __shfl_xor_sync(0xffffffff, tmax0, 1));
        tmax0 = fmaxf(tmax0, __shfl_xor_sync(0xffffffff, tmax0, 2));
        tmax1 = fmaxf(tmax1, __shfl_xor_sync(0xffffffff, tmax1, 1));
        tmax1 = fmaxf(tmax1, __shfl_xor_sync(0xffffffff, tmax1, 2));

        float nm0 = fmaxf(mrun0, tmax0), nm1 = fmaxf(mrun1, tmax1);
        float sc0 = __expf(mrun0 - nm0), sc1 = __expf(mrun1 - nm1);
        dr0 *= sc0; dr1 *= sc1;
        mrun0 = nm0; mrun1 = nm1;
        #pragma unroll
        for (int nb = 0; nb < 8; nb++) {
            acc_o[nb][0] *= sc0; acc_o[nb][1] *= sc0;
            acc_o[nb][2] *= sc1; acc_o[nb][3] *= sc1;
        }
        #pragma unroll
        for (int nb = 0; nb < 8; nb++) {
            float p0 = __expf(accs[nb][0] - nm0);
            float p1 = __expf(accs[nb][1] - nm0);
            float p2 = __expf(accs[nb][2] - nm1);
            float p3 = __expf(accs[nb][3] - nm1);
            accs[nb][0] = p0; accs[nb][1] = p1; accs[nb][2] = p2; accs[nb][3] = p3;
            dr0 += p0 + p1; dr1 += p2 + p3;
        }

        #pragma unroll
        for (int ks = 0; ks < 4; ks++) {
            unsigned ph[4], pl[4];
            ph[0] = packsplit(accs[2*ks][0],   accs[2*ks][1],   pl[0]);
            ph[1] = packsplit(accs[2*ks][2],   accs[2*ks][3],   pl[1]);
            ph[2] = packsplit(accs[2*ks+1][0], accs[2*ks+1][1], pl[2]);
            ph[3] = packsplit(accs[2*ks+1][2], accs[2*ks+1][3], pl[3]);
            #pragma unroll
            for (int nb2 = 0; nb2 < 4; nb2++) {
                unsigned int vh[4], vl[4];
                ldsm4t(vh, vhb + ks * 2304 + nb2 * 32);
                ldsm4t(vl, vlb + ks * 2304 + nb2 * 32);
                mma16816(acc_o[nb2*2],     ph, vh[0], vh[1]);
                mma16816(acc_o[nb2*2 + 1], ph, vh[2], vh[3]);
                mma16816(acc_o[nb2*2],     ph, vl[0], vl[1]);
                mma16816(acc_o[nb2*2 + 1], ph, vl[2], vl[3]);
                mma16816(acc_o[nb2*2],     pl, vh[0], vh[1]);
                mma16816(acc_o[nb2*2 + 1], pl, vh[2], vh[3]);
            }
        }
        __syncthreads();
    }

    dr0 += __shfl_xor_sync(0xffffffff, dr0, 1);
    dr0 += __shfl_xor_sync(0xffffffff, dr0, 2);
    dr1 += __shfl_xor_sync(0xffffffff, dr1, 1);
    dr1 += __shfl_xor_sync(0xffffffff, dr1, 2);

    if (r0 < LL) {
        float* dst = g_pacc + (((size_t)s * Bb + b) * LL + r0) * Cc;
        #pragma unroll
        for (int nb = 0; nb < 8; nb++)
            *(float2*)(dst + nb * 8 + tig * 2) = make_float2(acc_o[nb][0], acc_o[nb][1]);
        if (tig == 0) g_md[((size_t)s * Bb + b) * LL + r0] = make_float2(mrun0, dr0);
    }
    if (r1 < LL) {
        float* dst = g_pacc + (((size_t)s * Bb + b) * LL + r1) * Cc;
        #pragma unroll
        for (int nb = 0; nb < 8; nb++)
            *(float2*)(dst + nb * 8 + tig * 2) = make_float2(acc_o[nb][2], acc_o[nb][3]);
        if (tig == 0) g_md[((size_t)s * Bb + b) * LL + r1] = make_float2(mrun1, dr1);
    }
}

// ---------------- Kernel 3b: combine m-splits -> g_ns ----------------
__global__ __launch_bounds__(256)
void k_combine()
{
    int idx = blockIdx.x * 256 + threadIdx.x;
    if (idx >= Bb * LL * Cc) return;
    int c   = idx & 63;
    int row = idx >> 6;
    int l   = row % LL;
    int b   = row / LL;
    float2 md0 = g_md[(size_t)b * LL + l];
    float2 md1 = g_md[((size_t)Bb + b) * LL + l];
    float M  = fmaxf(md0.x, md1.x);
    float w0 = __expf(md0.x - M);
    float w1 = __expf(md1.x - M);
    float a0 = g_pacc[((size_t)b * LL + l) * Cc + c];
    float a1 = g_pacc[(((size_t)Bb + b) * LL + l) * Cc + c];
    g_ns[((size_t)b * Cc + c) * LL + l] =
        (w0 * a0 + w1 * a1) / (w0 * md0.y + w1 * md1.y);
}

// ---------------- Kernel 4: fold + epilogue ----------------
__global__ __launch_bounds__(256)
void k_epilogue(const float* __restrict__ x, const float* __restrict__ mask,
                const float* __restrict__ fg_g, const float* __restrict__ fg_b,
                const float* __restrict__ bg_g, const float* __restrict__ bg_b,
                float* __restrict__ out)
{
    int tid = blockIdx.x * 256 + threadIdx.x;
    int idx = tid * 4;
    int w0 = idx & 255;
    int h  = (idx >> 8) & 255;
    int c  = (idx >> 16) & 63;
    int b  = idx >> 22;
    int q  = w0 >> 2;

    float4 mv = *(const float4*)(mask + (size_t)b * HW + h * Ww + w0);
    float4 xv = *(const float4*)(x + idx);

    float bgG = 1.0f + bg_g[c], bgB = bg_b[c];
    float fgG = 1.0f + fg_g[c], fgB = fg_b[c];

    int ih_hi = h >> 2;  int ih_lo = ih_hi - 1;
    bool vh_hi = (ih_hi <= NUMS - 1), vh_lo = (ih_lo >= 0);
    int iw_hi = q;       int iw_lo = q - 1;
    bool vw_hi = (iw_hi <= NUMS - 1), vw_lo = (iw_lo >= 0);

    float m[4]  = {mv.x, mv.y, mv.z, mv.w};
    float xs[4] = {xv.x, xv.y, xv.z, xv.w};
    float xm[4], inm[4];
    #pragma unroll
    for (int p = 0; p < 4; p++) { inm[p] = 1.0f - m[p]; xm[p] = xs[p] * m[p]; }

    float sum[4] = {0.f, 0.f, 0.f, 0.f};
    size_t base = ((size_t)b * Cc + c) * LL;

    int ihv[2] = {ih_lo, ih_hi};  bool vav[2] = {vh_lo, vh_hi};
    int iwv[2] = {iw_lo, iw_hi};  bool vev[2] = {vw_lo, vw_hi};
    #pragma unroll
    for (int a = 0; a < 2; a++) {
        #pragma unroll
        for (int e = 0; e < 2; e++) {
            if (vav[a] && vev[e]) {
                int lp = ihv[a] * NUMS + iwv[e];
                float2 mi = g_mif[base + lp];
                float ns  = g_ns [base + lp];
                #pragma unroll
                for (int p = 0; p < 4; p++) {
                    float inf_ = (xm[p] - mi.x) * mi.y * m[p] + mi.x * inm[p];
                    sum[p] += inf_ * ns + ns;
                }
            }
        }
    }
    int cnt = ((int)vh_hi + (int)vh_lo) * ((int)vw_hi + (int)vw_lo);
    float invc = (cnt == 4) ? 0.25f : ((cnt == 2) ? 0.5f : 1.0f);

    float r[4];
    #pragma unroll
    for (int p = 0; p < 4; p++) {
        float ubg = (xs[p] * inm[p] * bgG + bgB) * inm[p];
        float val = (sum[p] * invc) * fgG + fgB;
        r[p] = val * m[p] + ubg;
    }
    *(float4*)(out + idx) = make_float4(r[0], r[1], r[2], r[3]);
}

// ---------------- launch ----------------
extern "C" void kernel_launch(void* const* d_in, const int* in_sizes, int n_in,
                              void* d_out, int out_size)
{
    const float* x       = (const float*)d_in[0];
    const float* mask    = (const float*)d_in[1];
    const float* fg_g    = (const float*)d_in[2];
    const float* fg_b    = (const float*)d_in[3];
    const float* bg_g    = (const float*)d_in[4];
    const float* bg_b    = (const float*)d_in[5];
    const float* w_fore  = (const float*)d_in[6];
    const float* w_back  = (const float*)d_in[7];
    const float* rpb     = (const float*)d_in[8];
    float* out = (float*)d_out;

    k_cells<<<(Bb * Cc * NCELL * NCELL) / 256, 256>>>(x, mask);
    k_pstats<<<(Bb * Cc * LL + 255) / 256, 256>>>();
    k_wsplit<<<dim3(64, 2), 256>>>(w_fore, w_back);
    k_gemm<<<dim3(32, Bb, 8), 128>>>(x, mask);
    k_prep<<<dim3(63, Bb), 256>>>();
    k_attn<<<dim3(32, Bb, 2), 256>>>(rpb);
    k_combine<<<(Bb * LL * Cc + 255) / 256, 256>>>();
    k_epilogue<<<(Bb * Cc * HW) / (256 * 4), 256>>>(x, mask, fg_g, fg_b, bg_g, bg_b, out);
}

// round 15
// speedup vs baseline: 1.0950x; 1.0141x over previous
#include <cuda_runtime.h>
#include <cuda_bf16.h>

#define Bb 2
#define Cc 64
#define Hh 256
#define Ww 256
#define HW (Hh*Ww)
#define NUMS 63
#define LL (NUMS*NUMS)          // 3969
#define LLP 4032
#define K2 64
#define EPSf 1e-5f
#define TBL_W (2*NUMS-1)        // 125
#define NCELL 64

typedef unsigned long long ull;
typedef __nv_bfloat16 bf16;

__device__ __forceinline__ unsigned int smaddr(const void* p){
    return (unsigned int)__cvta_generic_to_shared(p);
}
__device__ __forceinline__ void ldsm4(unsigned int* r, unsigned int addr){
    asm volatile("ldmatrix.sync.aligned.m8n8.x4.shared.b16 {%0,%1,%2,%3}, [%4];"
        : "=r"(r[0]), "=r"(r[1]), "=r"(r[2]), "=r"(r[3]) : "r"(addr));
}
__device__ __forceinline__ void ldsm4t(unsigned int* r, unsigned int addr){
    asm volatile("ldmatrix.sync.aligned.m8n8.x4.trans.shared.b16 {%0,%1,%2,%3}, [%4];"
        : "=r"(r[0]), "=r"(r[1]), "=r"(r[2]), "=r"(r[3]) : "r"(addr));
}
__device__ __forceinline__ void mma16816(float* d, const unsigned int* a,
                                         unsigned int b0, unsigned int b1){
    asm volatile("mma.sync.aligned.m16n8k16.row.col.f32.bf16.bf16.f32 "
        "{%0,%1,%2,%3}, {%4,%5,%6,%7}, {%8,%9}, {%0,%1,%2,%3};"
        : "+f"(d[0]), "+f"(d[1]), "+f"(d[2]), "+f"(d[3])
        : "r"(a[0]), "r"(a[1]), "r"(a[2]), "r"(a[3]), "r"(b0), "r"(b1));
}
__device__ __forceinline__ unsigned packsplit(float a, float b, unsigned &lo){
    __nv_bfloat162 h = __floats2bfloat162_rn(a, b);
    float ra = a - __bfloat162float(h.x);
    float rb = b - __bfloat162float(h.y);
    __nv_bfloat162 l2 = __floats2bfloat162_rn(ra, rb);
    lo = *(unsigned*)&l2;
    return *(unsigned*)&h;
}

// ---------------- device scratch ----------------
#define BCL (Bb*Cc*LL)
__device__ float2 g_mif [BCL];
__device__ float2 g_mib [BCL];
__device__ float  g_sbv [BCL];
__device__ float  g_tokp[8][BCL];
__device__ float  g_ns  [BCL];
__device__ float2 g_md  [2*Bb*LL];
__device__ float  g_pacc[2*Bb*LL*Cc];
__device__ float4 g_cellA[Bb*Cc*NCELL*NCELL];
__device__ float  g_cellM[Bb*NCELL*NCELL];
__device__ bf16 g_whT[2*4096*64];
__device__ bf16 g_wlT[2*4096*64];
__device__ bf16 g_tokfh[Bb*LL*64];
__device__ bf16 g_tokfl[Bb*LL*64];
__device__ bf16 g_tokbTh[Bb*64*LLP];
__device__ bf16 g_tokbTl[Bb*64*LLP];
__device__ bf16 g_vh[Bb*LLP*64];
__device__ bf16 g_vl[Bb*LLP*64];

// ---------------- Kernel 1a: per-cell raw moments ----------------
__global__ __launch_bounds__(256)
void k_cells(const float* __restrict__ x, const float* __restrict__ mask)
{
    int idx = blockIdx.x * 256 + threadIdx.x;
    int cj = idx & 63;
    int ci = (idx >> 6) & 63;
    int c  = (idx >> 12) & 63;
    int b  = idx >> 18;

    const float* xp = x    + (((size_t)b * Cc + c) * Hh + ci * 4) * Ww + cj * 4;
    const float* mp = mask + ((size_t)b * HW + ci * 4 * Ww) + cj * 4;

    float s1 = 0.f, s2 = 0.f, sm1 = 0.f, sm2 = 0.f, ms = 0.f;
    #pragma unroll
    for (int r = 0; r < 4; r++) {
        float4 xv = *(const float4*)(xp + r * Ww);
        float4 mv = *(const float4*)(mp + r * Ww);
        float vv[4] = {xv.x, xv.y, xv.z, xv.w};
        float mm[4] = {mv.x, mv.y, mv.z, mv.w};
        #pragma unroll
        for (int k = 0; k < 4; k++) {
            float v = vv[k], m = mm[k];
            s1 += v; s2 += v * v;
            sm1 += m * v; sm2 += m * v * v;
            ms += m;
        }
    }
    g_cellA[idx] = make_float4(s1, s2, sm1, sm2);
    if (c == 0) g_cellM[b * (NCELL*NCELL) + ci * NCELL + cj] = ms;
}

// ---------------- Kernel 1b: patch stats from 4 cells ----------------
__global__ __launch_bounds__(256)
void k_pstats()
{
    int idx = blockIdx.x * 256 + threadIdx.x;
    if (idx >= Bb * Cc * LL) return;
    int l  = idx % LL;
    int bc = idx / LL;
    int lh = l / NUMS, lw = l - lh * NUMS;
    int b  = bc >> 6;

    const float4* ca = g_cellA + (size_t)bc * (NCELL*NCELL);
    const float*  cm = g_cellM + (size_t)b * (NCELL*NCELL);
    int c00 = lh * NCELL + lw;

    float4 a0 = ca[c00],         a1 = ca[c00 + 1];
    float4 a2 = ca[c00 + NCELL], a3 = ca[c00 + NCELL + 1];
    float msum = cm[c00] + cm[c00 + 1] + cm[c00 + NCELL] + cm[c00 + NCELL + 1];

    float s1  = a0.x + a1.x + a2.x + a3.x;
    float s2  = a0.y + a1.y + a2.y + a3.y;
    float sm1 = a0.z + a1.z + a2.z + a3.z;
    float sm2 = a0.w + a1.w + a2.w + a3.w;

    float numf = msum;
    float numb = 64.0f - msum;
    float mf = sm1 / (numf + EPSf);
    float vf = (sm2 - 2.f * mf * sm1 + mf * mf * numf) / (numf + EPSf);
    float sb1 = s1 - sm1, sb2 = s2 - sm2;
    float mb = sb1 / (numb + EPSf);
    float vb = (sb2 - 2.f * mb * sb1 + mb * mb * numb) / (numb + EPSf);

    g_mif[idx] = make_float2(mf, 1.0f / vf);
    g_mib[idx] = make_float2(mb, 1.0f / vb);
    int c = bc & 63;
    g_sbv[((size_t)b * LL + l) * Cc + c] = vb;
}

// ---------------- Kernel 1c: W -> transposed bf16 split ----------------
__global__ __launch_bounds__(256)
void k_wsplit(const float* __restrict__ wf, const float* __restrict__ wb)
{
    int type = blockIdx.y;
    int ck0  = blockIdx.x * 64;
    const float* w = type ? wb : wf;
    __shared__ float tile[64][65];
    int t = threadIdx.x;
    int d = t >> 2, q = t & 3;
    #pragma unroll
    for (int i = 0; i < 4; i++) {
        float4 v = *(const float4*)&w[(size_t)d * 4096 + ck0 + q * 16 + i * 4];
        tile[q*16 + i*4 + 0][d] = v.x;
        tile[q*16 + i*4 + 1][d] = v.y;
        tile[q*16 + i*4 + 2][d] = v.z;
        tile[q*16 + i*4 + 3][d] = v.w;
    }
    __syncthreads();
    int ck = t >> 2, q2 = t & 3, d0 = q2 * 16;
    bf16 hv[16], lv[16];
    #pragma unroll
    for (int j = 0; j < 16; j++) {
        float v = tile[ck][d0 + j];
        bf16 h = __float2bfloat16(v);
        hv[j] = h;
        lv[j] = __float2bfloat16(v - __bfloat162float(h));
    }
    size_t o = ((size_t)type * 4096 + ck0 + ck) * 64 + d0;
    *(uint4*)&g_whT[o]     = *(uint4*)&hv[0];
    *(uint4*)&g_whT[o + 8] = *(uint4*)&hv[8];
    *(uint4*)&g_wlT[o]     = *(uint4*)&lv[0];
    *(uint4*)&g_wlT[o + 8] = *(uint4*)&lv[8];
}

// ---------------- Kernel 2: token GEMM, double-buffered pipeline ----------------
// grid (32, Bb, 8): z = type*4 + kq. Block: 128L x 64D x 1024K (32 phases).
__global__ __launch_bounds__(128)
void k_gemm(const float* __restrict__ x, const float* __restrict__ mask)
{
    int tile  = blockIdx.x;
    int b     = blockIdx.y;
    int type  = blockIdx.z >> 2;
    int kq    = blockIdx.z & 3;
    const float2* g_mi = type ? g_mib : g_mif;
    float* g_tk = g_tokp[blockIdx.z];

    int l0 = tile * 128;
    int t  = threadIdx.x;
    int lane = t & 31, warp = t >> 5;

    __shared__ __align__(16) bf16 Ah[2][128][40];
    __shared__ __align__(16) bf16 Al[2][128][40];
    __shared__ __align__(16) bf16 Wh[2][32][72];
    __shared__ __align__(16) bf16 Wl[2][32][72];

    int lgl = l0 + t;
    int lg  = (lgl < LL) ? lgl : (LL - 1);
    int lh = lg / NUMS, lw = lg - lh * NUMS;

    unsigned int mb0 = 0, mb1 = 0;
    {
        const float* mp = mask + (size_t)b * HW + (lh * 4) * Ww + lw * 4;
        #pragma unroll
        for (int r = 0; r < 8; r++) {
            float4 a = *(const float4*)(mp + r * Ww);
            float4 bq = *(const float4*)(mp + r * Ww + 4);
            float mv[8] = {a.x,a.y,a.z,a.w,bq.x,bq.y,bq.z,bq.w};
            unsigned int bits = 0;
            #pragma unroll
            for (int kw = 0; kw < 8; kw++) {
                bool on = mv[kw] > 0.5f;
                if (type) on = !on;
                bits |= (on ? 1u : 0u) << (((r & 3) * 8) + kw);
            }
            if (r < 4) mb0 |= bits; else mb1 |= bits;
        }
    }

    int wrow = t >> 2, wq = t & 3;
    int c0 = kq * 16;

    float acc[2][8][4];
    #pragma unroll
    for (int f = 0; f < 2; f++)
        #pragma unroll
        for (int i = 0; i < 8; i++)
            #pragma unroll
            for (int j = 0; j < 4; j++) acc[f][i][j] = 0.f;

    // fragment addresses per buffer
    unsigned int aaddr_h[2][2][2], aaddr_l[2][2][2];   // [buf][frag][ks]
    unsigned int baddr_h[2][2][4], baddr_l[2][2][4];   // [buf][ks][nb2]
    {
        int acol = (lane >> 4) << 3;
        int brow = lane & 15;
        int bcol = (lane >> 4) << 3;
        #pragma unroll
        for (int bu = 0; bu < 2; bu++) {
            #pragma unroll
            for (int f = 0; f < 2; f++) {
                int arow = warp * 32 + f * 16 + (lane & 15);
                #pragma unroll
                for (int ks = 0; ks < 2; ks++) {
                    aaddr_h[bu][f][ks] = smaddr(&Ah[bu][arow][ks * 16 + acol]);
                    aaddr_l[bu][f][ks] = smaddr(&Al[bu][arow][ks * 16 + acol]);
                }
            }
            #pragma unroll
            for (int ks = 0; ks < 2; ks++)
                #pragma unroll
                for (int nb2 = 0; nb2 < 4; nb2++) {
                    baddr_h[bu][ks][nb2] = smaddr(&Wh[bu][ks * 16 + brow][nb2 * 16 + bcol]);
                    baddr_l[bu][ks][nb2] = smaddr(&Wl[bu][ks * 16 + brow][nb2 * 16 + bcol]);
                }
        }
    }

    // gmem prefetch registers
    float4 xr[8];           // 4 rows x 2 (8 cols)
    float2 mi;
    uint4 wh0, wh1, wl0, wl1;

    auto LD = [&](int p) {
        int c = c0 + (p >> 1), sub = p & 1;
        const float* xp = x + (((size_t)b * Cc + c) * Hh + lh * 4 + sub * 4) * Ww + lw * 4;
        #pragma unroll
        for (int r = 0; r < 4; r++) {
            xr[2*r]   = *(const float4*)(xp + r * Ww);
            xr[2*r+1] = *(const float4*)(xp + r * Ww + 4);
        }
        mi = g_mi[((size_t)b * Cc + c) * LL + lg];
        size_t o = ((size_t)type * 4096 + c * 64 + sub * 32 + wrow) * 64 + wq * 16;
        wh0 = *(const uint4*)&g_whT[o];
        wh1 = *(const uint4*)&g_whT[o + 8];
        wl0 = *(const uint4*)&g_wlT[o];
        wl1 = *(const uint4*)&g_wlT[o + 8];
    };

    auto STAGE = [&](int p, int bu) {
        int sub = p & 1;
        float negmuis = -mi.x * mi.y;
        unsigned int bits = sub ? mb1 : mb0;
        #pragma unroll
        for (int r = 0; r < 4; r++) {
            float xv[8] = {xr[2*r].x, xr[2*r].y, xr[2*r].z, xr[2*r].w,
                           xr[2*r+1].x, xr[2*r+1].y, xr[2*r+1].z, xr[2*r+1].w};
            #pragma unroll
            for (int i = 0; i < 4; i++) {
                bool on0 = (bits >> (r * 8 + 2*i)) & 1u;
                bool on1 = (bits >> (r * 8 + 2*i + 1)) & 1u;
                float v0 = on0 ? fmaf(xv[2*i],   mi.y, negmuis) : mi.x;
                float v1 = on1 ? fmaf(xv[2*i+1], mi.y, negmuis) : mi.x;
                __nv_bfloat162 h2 = __floats2bfloat162_rn(v0, v1);
                float2 hf = __bfloat1622float2(h2);
                __nv_bfloat162 l2 = __floats2bfloat162_rn(v0 - hf.x, v1 - hf.y);
                *(unsigned*)&Ah[bu][t][r * 8 + 2*i] = *(unsigned*)&h2;
                *(unsigned*)&Al[bu][t][r * 8 + 2*i] = *(unsigned*)&l2;
            }
        }
        *(uint4*)&Wh[bu][wrow][wq * 16]     = wh0;
        *(uint4*)&Wh[bu][wrow][wq * 16 + 8] = wh1;
        *(uint4*)&Wl[bu][wrow][wq * 16]     = wl0;
        *(uint4*)&Wl[bu][wrow][wq * 16 + 8] = wl1;
    };

    LD(0);
    STAGE(0, 0);
    __syncthreads();

    for (int p = 0; p < 32; p++) {
        int bu = p & 1;
        if (p < 31) LD(p + 1);   // gmem latency hides under the mma block below

        #pragma unroll
        for (int ks = 0; ks < 2; ks++) {
            unsigned int ah[2][4], alr[2][4];
            #pragma unroll
            for (int f = 0; f < 2; f++) {
                ldsm4(ah[f],  aaddr_h[bu][f][ks]);
                ldsm4(alr[f], aaddr_l[bu][f][ks]);
            }
            #pragma unroll
            for (int nb2 = 0; nb2 < 4; nb2++) {
                unsigned int bh[4], blr[4];
                ldsm4t(bh,  baddr_h[bu][ks][nb2]);
                ldsm4t(blr, baddr_l[bu][ks][nb2]);
                #pragma unroll
                for (int f = 0; f < 2; f++) {
                    mma16816(acc[f][nb2*2],     ah[f],  bh[0],  bh[1]);
                    mma16816(acc[f][nb2*2 + 1], ah[f],  bh[2],  bh[3]);
                    mma16816(acc[f][nb2*2],     ah[f],  blr[0], blr[1]);
                    mma16816(acc[f][nb2*2 + 1], ah[f],  blr[2], blr[3]);
                    mma16816(acc[f][nb2*2],     alr[f], bh[0],  bh[1]);
                    mma16816(acc[f][nb2*2 + 1], alr[f], bh[2],  bh[3]);
                }
            }
        }

        if (p < 31) {
            STAGE(p + 1, bu ^ 1);   // write other buffer (no reader yet)
            __syncthreads();        // one barrier per phase
        }
    }

    int grp = lane >> 2, tig = lane & 3;
    #pragma unroll
    for (int f = 0; f < 2; f++) {
        #pragma unroll
        for (int nb = 0; nb < 8; nb++) {
            int d = nb * 8 + tig * 2;
            int lr0 = l0 + warp * 32 + f * 16 + grp;
            if (lr0 < LL)
                *(float2*)(g_tk + ((size_t)b * LL + lr0) * Cc + d) = make_float2(acc[f][nb][0], acc[f][nb][1]);
            int lr1 = lr0 + 8;
            if (lr1 < LL)
                *(float2*)(g_tk + ((size_t)b * LL + lr1) * Cc + d) = make_float2(acc[f][nb][2], acc[f][nb][3]);
        }
    }
}

// ---------------- Kernel 2b: merge 4 partials/type + emit bf16-split Q/K^T/V ----------------
__global__ __launch_bounds__(256)
void k_prep()
{
    int b  = blockIdx.y;
    int l0 = blockIdx.x * 64;
    int t  = threadIdx.x;
    __shared__ float tb[64][65];

    int r = t >> 2, q = t & 3, c0 = q * 16;
    int l = l0 + r;
    bool valid = l < LL;

    float tf[16], tbv[16], sv[16];
    if (valid) {
        size_t o = ((size_t)b * LL + l) * 64 + c0;
        #pragma unroll
        for (int i = 0; i < 16; i += 4) {
            float4 a0 = *(const float4*)&g_tokp[0][o + i];
            float4 a1 = *(const float4*)&g_tokp[1][o + i];
            float4 a2 = *(const float4*)&g_tokp[2][o + i];
            float4 a3 = *(const float4*)&g_tokp[3][o + i];
            tf[i]   = a0.x + a1.x + a2.x + a3.x;
            tf[i+1] = a0.y + a1.y + a2.y + a3.y;
            tf[i+2] = a0.z + a1.z + a2.z + a3.z;
            tf[i+3] = a0.w + a1.w + a2.w + a3.w;
            float4 b0 = *(const float4*)&g_tokp[4][o + i];
            float4 b1 = *(const float4*)&g_tokp[5][o + i];
            float4 b2 = *(const float4*)&g_tokp[6][o + i];
            float4 b3 = *(const float4*)&g_tokp[7][o + i];
            tbv[i]   = b0.x + b1.x + b2.x + b3.x;
            tbv[i+1] = b0.y + b1.y + b2.y + b3.y;
            tbv[i+2] = b0.z + b1.z + b2.z + b3.z;
            tbv[i+3] = b0.w + b1.w + b2.w + b3.w;
            float4 s = *(const float4*)&g_sbv[o + i];
            sv[i] = s.x; sv[i+1] = s.y; sv[i+2] = s.z; sv[i+3] = s.w;
        }
    } else {
        #pragma unroll
        for (int i = 0; i < 16; i++) { tf[i] = 0.f; tbv[i] = 0.f; sv[i] = 0.f; }
    }

    if (valid) {
        bf16 h[16], lo[16];
        #pragma unroll
        for (int i = 0; i < 16; i++) {
            bf16 hh = __float2bfloat16(tf[i]);
            h[i] = hh; lo[i] = __float2bfloat16(tf[i] - __bfloat162float(hh));
        }
        size_t o = ((size_t)b * LL + l) * 64 + c0;
        *(uint4*)&g_tokfh[o]     = *(uint4*)&h[0];
        *(uint4*)&g_tokfh[o + 8] = *(uint4*)&h[8];
        *(uint4*)&g_tokfl[o]     = *(uint4*)&lo[0];
        *(uint4*)&g_tokfl[o + 8] = *(uint4*)&lo[8];
    }
    {
        bf16 h[16], lo[16];
        #pragma unroll
        for (int i = 0; i < 16; i++) {
            bf16 hh = __float2bfloat16(sv[i]);
            h[i] = hh; lo[i] = __float2bfloat16(sv[i] - __bfloat162float(hh));
        }
        size_t o = ((size_t)b * LLP + l) * 64 + c0;
        *(uint4*)&g_vh[o]     = *(uint4*)&h[0];
        *(uint4*)&g_vh[o + 8] = *(uint4*)&h[8];
        *(uint4*)&g_vl[o]     = *(uint4*)&lo[0];
        *(uint4*)&g_vl[o + 8] = *(uint4*)&lo[8];
    }
    #pragma unroll
    for (int i = 0; i < 16; i++) tb[r][c0 + i] = tbv[i];
    __syncthreads();

    int c = t >> 2, lq = t & 3;
    bf16 h[16], lo[16];
    #pragma unroll
    for (int j = 0; j < 16; j++) {
        float v = tb[lq * 16 + j][c];
        bf16 hh = __float2bfloat16(v);
        h[j] = hh; lo[j] = __float2bfloat16(v - __bfloat162float(hh));
    }
    size_t o = ((size_t)b * 64 + c) * LLP + l0 + lq * 16;
    *(uint4*)&g_tokbTh[o]     = *(uint4*)&h[0];
    *(uint4*)&g_tokbTh[o + 8] = *(uint4*)&h[8];
    *(uint4*)&g_tokbTl[o]     = *(uint4*)&lo[0];
    *(uint4*)&g_tokbTl[o + 8] = *(uint4*)&lo[8];
}

// ---------------- Kernel 3: attention via mma.sync (FA pattern, unchanged) ----------------
__global__ __launch_bounds__(256)
void k_attn(const float* __restrict__ rpb)
{
    int b = blockIdx.y, s = blockIdx.z;
    int l0 = blockIdx.x * 128;
    int t = threadIdx.x;
    int lane = t & 31, warp = t >> 5;
    int grp = lane >> 2, tig = lane & 3;

    __shared__ __align__(16) char sbuf[36864];
    __shared__ int rpish[64];
    bf16 (*Qh)[72] = (bf16(*)[72])sbuf;
    bf16 (*Ql)[72] = (bf16(*)[72])(sbuf + 18432);
    bf16 (*Kh)[72] = (bf16(*)[72])sbuf;
    bf16 (*Kl)[72] = (bf16(*)[72])(sbuf + 9216);
    bf16 (*Vh)[72] = (bf16(*)[72])(sbuf + 18432);
    bf16 (*Vl)[72] = (bf16(*)[72])(sbuf + 27648);

    #pragma unroll
    for (int i = 0; i < 4; i++) {
        int chunk = t + i * 256;
        int row = chunk >> 3, off = (chunk & 7) * 8;
        int lr = min(l0 + row, LL - 1);
        *(uint4*)&Qh[row][off] = *(const uint4*)&g_tokfh[((size_t)b * LL + lr) * 64 + off];
        *(uint4*)&Ql[row][off] = *(const uint4*)&g_tokfl[((size_t)b * LL + lr) * 64 + off];
    }
    __syncthreads();
    unsigned qh[4][4], ql[4][4];
    {
        int ar = warp * 16 + (lane & 15), ac = (lane >> 4) * 8;
        #pragma unroll
        for (int ks = 0; ks < 4; ks++) {
            ldsm4(qh[ks], smaddr(&Qh[ar][ks * 16 + ac]));
            ldsm4(ql[ks], smaddr(&Ql[ar][ks * 16 + ac]));
        }
    }
    __syncthreads();

    int r0 = l0 + warp * 16 + grp;
    int r1 = r0 + 8;
    int lr0 = min(r0, LL - 1), lr1 = min(r1, LL - 1);
    int rc0, rc1;
    { int lh = lr0 / NUMS, lw = lr0 - lh * NUMS; rc0 = (lh + 62) * TBL_W + (lw + 62); }
    { int lh = lr1 / NUMS, lw = lr1 - lh * NUMS; rc1 = (lh + 62) * TBL_W + (lw + 62); }

    float acc_o[8][4];
    #pragma unroll
    for (int i = 0; i < 8; i++)
        #pragma unroll
        for (int j = 0; j < 4; j++) acc_o[i][j] = 0.f;
    float mrun0 = -1e30f, mrun1 = -1e30f, dr0 = 0.f, dr1 = 0.f;

    unsigned int khb, klb, vhb, vlb;
    {
        unsigned int base = (lane & 15) * 144 + (lane >> 4) * 16;
        khb = smaddr(Kh) + base; klb = smaddr(Kl) + base;
        vhb = smaddr(Vh) + base; vlb = smaddr(Vl) + base;
    }

    int NT = 31 + s;
    for (int tt = 0; tt < NT; tt++) {
        int m0 = (s ? 1984 : 0) + tt * 64;
        #pragma unroll
        for (int i = 0; i < 2; i++) {
            int chunk = t + i * 256;
            int row = chunk >> 3, off = (chunk & 7) * 8;
            *(uint4*)&Kh[row][off] = *(const uint4*)&g_tokbTh[((size_t)b * 64 + row) * LLP + m0 + off];
            *(uint4*)&Kl[row][off] = *(const uint4*)&g_tokbTl[((size_t)b * 64 + row) * LLP + m0 + off];
            *(uint4*)&Vh[row][off] = *(const uint4*)&g_vh[((size_t)b * LLP + m0 + row) * 64 + off];
            *(uint4*)&Vl[row][off] = *(const uint4*)&g_vl[((size_t)b * LLP + m0 + row) * 64 + off];
        }
        if (t < 64) {
            int m = m0 + t;
            if (m < LL) { int mh = m / NUMS; rpish[t] = mh * TBL_W + (m - mh * NUMS); }
            else rpish[t] = -1;
        }
        __syncthreads();

        float accs[8][4];
        #pragma unroll
        for (int i = 0; i < 8; i++)
            #pragma unroll
            for (int j = 0; j < 4; j++) accs[i][j] = 0.f;
        #pragma unroll
        for (int ks = 0; ks < 4; ks++) {
            #pragma unroll
            for (int nb2 = 0; nb2 < 4; nb2++) {
                unsigned int bh[4], bl[4];
                ldsm4t(bh, khb + ks * 2304 + nb2 * 32);
                ldsm4t(bl, klb + ks * 2304 + nb2 * 32);
                mma16816(accs[nb2*2],     qh[ks], bh[0], bh[1]);
                mma16816(accs[nb2*2 + 1], qh[ks], bh[2], bh[3]);
                mma16816(accs[nb2*2],     qh[ks], bl[0], bl[1]);
                mma16816(accs[nb2*2 + 1], qh[ks], bl[2], bl[3]);
                mma16816(accs[nb2*2],     ql[ks], bh[0], bh[1]);
                mma16816(accs[nb2*2 + 1], ql[ks], bh[2], bh[3]);
            }
        }

        float tmax0 = -1e30f, tmax1 = -1e30f;
        #pragma unroll
        for (int nb = 0; nb < 8; nb++) {
            #pragma unroll
            for (int e = 0; e < 4; e++) {
                int off = rpish[nb * 8 + tig * 2 + (e & 1)];
                float bias = (off >= 0) ? __ldg(rpb + ((e < 2) ? rc0 : rc1) - off) : -1e30f;
                float v = accs[nb][e] + bias;
                accs[nb][e] = v;
                if (e < 2) tmax0 = fmaxf(tmax0, v); else tmax1 = fmaxf(tmax1, v);
            }
        }
        tmax0 = fmaxf(tmax0, __shfl_xor_sync(0xffffffff, tmax0, 1));
        tmax0 = fmaxf(tmax0, __shfl_xor_sync(0xffffffff, tmax0, 2));
        tmax1 = fmaxf(tmax1, __shfl_xor_sync(0xffffffff, tmax1, 1));
        tmax1 = fmaxf(tmax1, __shfl_xor_sync(0xffffffff, tmax1, 2));

        float nm0 = fmaxf(mrun0, tmax0), nm1 = fmaxf(mrun1, tmax1);
        float sc0 = __expf(mrun0 - nm0), sc1 = __expf(mrun1 - nm1);
        dr0 *= sc0; dr1 *= sc1;
        mrun0 = nm0; mrun1 = nm1;
        #pragma unroll
        for (int nb = 0; nb < 8; nb++) {
            acc_o[nb][0] *= sc0; acc_o[nb][1] *= sc0;
            acc_o[nb][2] *= sc1; acc_o[nb][3] *= sc1;
        }
        #pragma unroll
        for (int nb = 0; nb < 8; nb++) {
            float p0 = __expf(accs[nb][0] - nm0);
            float p1 = __expf(accs[nb][1] - nm0);
            float p2 = __expf(accs[nb][2] - nm1);
            float p3 = __expf(accs[nb][3] - nm1);
            accs[nb][0] = p0; accs[nb][1] = p1; accs[nb][2] = p2; accs[nb][3] = p3;
            dr0 += p0 + p1; dr1 += p2 + p3;
        }

        #pragma unroll
        for (int ks = 0; ks < 4; ks++) {
            unsigned ph[4], pl[4];
            ph[0] = packsplit(accs[2*ks][0],   accs[2*ks][1],   pl[0]);
            ph[1] = packsplit(accs[2*ks][2],   accs[2*ks][3],   pl[1]);
            ph[2] = packsplit(accs[2*ks+1][0], accs[2*ks+1][1], pl[2]);
            ph[3] = packsplit(accs[2*ks+1][2], accs[2*ks+1][3], pl[3]);
            #pragma unroll
            for (int nb2 = 0; nb2 < 4; nb2++) {
                unsigned int vh[4], vl[4];
                ldsm4t(vh, vhb + ks * 2304 + nb2 * 32);
                ldsm4t(vl, vlb + ks * 2304 + nb2 * 32);
                mma16816(acc_o[nb2*2],     ph, vh[0], vh[1]);
                mma16816(acc_o[nb2*2 + 1], ph, vh[2], vh[3]);
                mma16816(acc_o[nb2*2],     ph, vl[0], vl[1]);
                mma16816(acc_o[nb2*2 + 1], ph, vl[2], vl[3]);
                mma16816(acc_o[nb2*2],     pl, vh[0], vh[1]);
                mma16816(acc_o[nb2*2 + 1], pl, vh[2], vh[3]);
            }
        }
        __syncthreads();
    }

    dr0 += __shfl_xor_sync(0xffffffff, dr0, 1);
    dr0 += __shfl_xor_sync(0xffffffff, dr0, 2);
    dr1 += __shfl_xor_sync(0xffffffff, dr1, 1);
    dr1 += __shfl_xor_sync(0xffffffff, dr1, 2);

    if (r0 < LL) {
        float* dst = g_pacc + (((size_t)s * Bb + b) * LL + r0) * Cc;
        #pragma unroll
        for (int nb = 0; nb < 8; nb++)
            *(float2*)(dst + nb * 8 + tig * 2) = make_float2(acc_o[nb][0], acc_o[nb][1]);
        if (tig == 0) g_md[((size_t)s * Bb + b) * LL + r0] = make_float2(mrun0, dr0);
    }
    if (r1 < LL) {
        float* dst = g_pacc + (((size_t)s * Bb + b) * LL + r1) * Cc;
        #pragma unroll
        for (int nb = 0; nb < 8; nb++)
            *(float2*)(dst + nb * 8 + tig * 2) = make_float2(acc_o[nb][2], acc_o[nb][3]);
        if (tig == 0) g_md[((size_t)s * Bb + b) * LL + r1] = make_float2(mrun1, dr1);
    }
}

// ---------------- Kernel 3b: combine m-splits -> g_ns ----------------
__global__ __launch_bounds__(256)
void k_combine()
{
    int idx = blockIdx.x * 256 + threadIdx.x;
    if (idx >= Bb * LL * Cc) return;
    int c   = idx & 63;
    int row = idx >> 6;
    int l   = row % LL;
    int b   = row / LL;
    float2 md0 = g_md[(size_t)b * LL + l];
    float2 md1 = g_md[((size_t)Bb + b) * LL + l];
    float M  = fmaxf(md0.x, md1.x);
    float w0 = __expf(md0.x - M);
    float w1 = __expf(md1.x - M);
    float a0 = g_pacc[((size_t)b * LL + l) * Cc + c];
    float a1 = g_pacc[(((size_t)Bb + b) * LL + l) * Cc + c];
    g_ns[((size_t)b * Cc + c) * LL + l] =
        (w0 * a0 + w1 * a1) / (w0 * md0.y + w1 * md1.y);
}

// ---------------- Kernel 4: fold + epilogue ----------------
__global__ __launch_bounds__(256)
void k_epilogue(const float* __restrict__ x, const float* __restrict__ mask,
                const float* __restrict__ fg_g, const float* __restrict__ fg_b,
                const float* __restrict__ bg_g, const float* __restrict__ bg_b,
                float* __restrict__ out)
{
    int tid = blockIdx.x * 256 + threadIdx.x;
    int idx = tid * 4;
    int w0 = idx & 255;
    int h  = (idx >> 8) & 255;
    int c  = (idx >> 16) & 63;
    int b  = idx >> 22;
    int q  = w0 >> 2;

    float4 mv = *(const float4*)(mask + (size_t)b * HW + h * Ww + w0);
    float4 xv = *(const float4*)(x + idx);

    float bgG = 1.0f + bg_g[c], bgB = bg_b[c];
    float fgG = 1.0f + fg_g[c], fgB = fg_b[c];

    int ih_hi = h >> 2;  int ih_lo = ih_hi - 1;
    bool vh_hi = (ih_hi <= NUMS - 1), vh_lo = (ih_lo >= 0);
    int iw_hi = q;       int iw_lo = q - 1;
    bool vw_hi = (iw_hi <= NUMS - 1), vw_lo = (iw_lo >= 0);

    float m[4]  = {mv.x, mv.y, mv.z, mv.w};
    float xs[4] = {xv.x, xv.y, xv.z, xv.w};
    float xm[4], inm[4];
    #pragma unroll
    for (int p = 0; p < 4; p++) { inm[p] = 1.0f - m[p]; xm[p] = xs[p] * m[p]; }

    float sum[4] = {0.f, 0.f, 0.f, 0.f};
    size_t base = ((size_t)b * Cc + c) * LL;

    int ihv[2] = {ih_lo, ih_hi};  bool vav[2] = {vh_lo, vh_hi};
    int iwv[2] = {iw_lo, iw_hi};  bool vev[2] = {vw_lo, vw_hi};
    #pragma unroll
    for (int a = 0; a < 2; a++) {
        #pragma unroll
        for (int e = 0; e < 2; e++) {
            if (vav[a] && vev[e]) {
                int lp = ihv[a] * NUMS + iwv[e];
                float2 mi = g_mif[base + lp];
                float ns  = g_ns [base + lp];
                #pragma unroll
                for (int p = 0; p < 4; p++) {
                    float inf_ = (xm[p] - mi.x) * mi.y * m[p] + mi.x * inm[p];
                    sum[p] += inf_ * ns + ns;
                }
            }
        }
    }
    int cnt = ((int)vh_hi + (int)vh_lo) * ((int)vw_hi + (int)vw_lo);
    float invc = (cnt == 4) ? 0.25f : ((cnt == 2) ? 0.5f : 1.0f);

    float r[4];
    #pragma unroll
    for (int p = 0; p < 4; p++) {
        float ubg = (xs[p] * inm[p] * bgG + bgB) * inm[p];
        float val = (sum[p] * invc) * fgG + fgB;
        r[p] = val * m[p] + ubg;
    }
    *(float4*)(out + idx) = make_float4(r[0], r[1], r[2], r[3]);
}

// ---------------- launch ----------------
extern "C" void kernel_launch(void* const* d_in, const int* in_sizes, int n_in,
                              void* d_out, int out_size)
{
    const float* x       = (const float*)d_in[0];
    const float* mask    = (const float*)d_in[1];
    const float* fg_g    = (const float*)d_in[2];
    const float* fg_b    = (const float*)d_in[3];
    const float* bg_g    = (const float*)d_in[4];
    const float* bg_b    = (const float*)d_in[5];
    const float* w_fore  = (const float*)d_in[6];
    const float* w_back  = (const float*)d_in[7];
    const float* rpb     = (const float*)d_in[8];
    float* out = (float*)d_out;

    k_cells<<<(Bb * Cc * NCELL * NCELL) / 256, 256>>>(x, mask);
    k_pstats<<<(Bb * Cc * LL + 255) / 256, 256>>>();
    k_wsplit<<<dim3(64, 2), 256>>>(w_fore, w_back);
    k_gemm<<<dim3(32, Bb, 8), 128>>>(x, mask);
    k_prep<<<dim3(63, Bb), 256>>>();
    k_attn<<<dim3(32, Bb, 2), 256>>>(rpb);
    k_combine<<<(Bb * LL * Cc + 255) / 256, 256>>>();
    k_epilogue<<<(Bb * Cc * HW) / (256 * 4), 256>>>(x, mask, fg_g, fg_b, bg_g, bg_b, out);
}